// round 1
// baseline (speedup 1.0000x reference)
#include <cuda_runtime.h>
#include <math.h>

#define T_LEN   8196
#define WIN     8
#define STRIDE  4
#define NW      2048
#define BATCH   4096      // both sequences fused
#define IN_F    72
#define HID     128
#define G3      384
#define FEAT    30
#define STEPS   8
#define INF_V   1e10f

// ---------------- static scratch (no allocations allowed) ----------------
__device__ float g_seq  [STEPS * BATCH * IN_F];   // 9.4 MB
__device__ float g_gi   [STEPS * BATCH * G3];     // 50 MB (reused by layer 2)
__device__ float g_gh   [BATCH * G3];             // 6.3 MB
__device__ float g_h1all[STEPS * BATCH * HID];    // 16.8 MB
__device__ float g_hA   [BATCH * HID];
__device__ float g_hB   [BATCH * HID];
__device__ float g_hz   [BATCH * HID];            // zeros (h0)
__device__ float g_feat [BATCH * FEAT];
__device__ float g_Dd   [4096 * 2048];            // diagonal-major D, 32 MB

// ---------------- window extraction ----------------
__global__ void build_seq_kernel(const float* __restrict__ x,
                                 const float* __restrict__ y) {
    int idx = blockIdx.x * blockDim.x + threadIdx.x;
    const int total = STEPS * BATCH * IN_F;
    if (idx >= total) return;
    int f = idx % IN_F;
    int b = (idx / IN_F) % BATCH;
    int s = idx / (IN_F * BATCH);
    const float* src = (b < NW) ? x : y;
    int w = b & (NW - 1);
    int t = w * STRIDE + s;
    g_seq[idx] = src[(size_t)f * T_LEN + t];   // f = j*3+c, layout (J,3,T) flattens to f*T
}

__global__ void zero_kernel(float* __restrict__ p, int n) {
    int idx = blockIdx.x * blockDim.x + threadIdx.x;
    if (idx < n) p[idx] = 0.f;
}

// ---------------- SGEMM: C[M,N] = A[M,K] @ B[N,K]^T + bias[N] ----------------
// All dims used are exact multiples of the tiles (no bounds checks needed).
template<int BM, int BN, int BK, int TM, int TN>
__global__ void __launch_bounds__((BM/TM)*(BN/TN))
sgemm_tn(const float* __restrict__ A, const float* __restrict__ Bw,
         const float* __restrict__ bias, float* __restrict__ C,
         int M, int N, int K) {
    __shared__ float As[BK][BM];
    __shared__ float Bs[BK][BN];
    const int nThreads = (BM/TM)*(BN/TN);
    const int tid = threadIdx.x;
    const int rb = blockIdx.y * BM;
    const int cb = blockIdx.x * BN;
    const int tx = tid % (BN/TN);
    const int ty = tid / (BN/TN);

    float acc[TM][TN];
#pragma unroll
    for (int i = 0; i < TM; i++)
#pragma unroll
        for (int j = 0; j < TN; j++) acc[i][j] = 0.f;

    for (int k0 = 0; k0 < K; k0 += BK) {
#pragma unroll
        for (int idx = tid; idx < BM * BK; idx += nThreads) {
            int r = idx / BK, kk = idx % BK;
            As[kk][r] = A[(size_t)(rb + r) * K + k0 + kk];
        }
#pragma unroll
        for (int idx = tid; idx < BN * BK; idx += nThreads) {
            int r = idx / BK, kk = idx % BK;
            Bs[kk][r] = Bw[(size_t)(cb + r) * K + k0 + kk];
        }
        __syncthreads();
#pragma unroll
        for (int kk = 0; kk < BK; kk++) {
            float ra[TM], rbv[TN];
#pragma unroll
            for (int i = 0; i < TM; i++) ra[i] = As[kk][ty * TM + i];
#pragma unroll
            for (int j = 0; j < TN; j++) rbv[j] = Bs[kk][tx * TN + j];
#pragma unroll
            for (int i = 0; i < TM; i++)
#pragma unroll
                for (int j = 0; j < TN; j++)
                    acc[i][j] += ra[i] * rbv[j];
        }
        __syncthreads();
    }
#pragma unroll
    for (int i = 0; i < TM; i++) {
        int row = rb + ty * TM + i;
#pragma unroll
        for (int j = 0; j < TN; j++) {
            int col = cb + tx * TN + j;
            C[(size_t)row * N + col] = acc[i][j] + bias[col];
        }
    }
}

// ---------------- GRU pointwise combine ----------------
__global__ void gru_combine_kernel(const float* __restrict__ gi,
                                   const float* __restrict__ hprev,
                                   float* __restrict__ hout,
                                   float* __restrict__ hstore) {
    int idx = blockIdx.x * blockDim.x + threadIdx.x;
    if (idx >= BATCH * HID) return;
    int b = idx >> 7;
    int u = idx & (HID - 1);
    const float* gib = gi + (size_t)b * G3;
    const float* ghb = g_gh + (size_t)b * G3;
    float ir = gib[u], iz = gib[u + HID], in_ = gib[u + 2 * HID];
    float hr = ghb[u], hz = ghb[u + HID], hn  = ghb[u + 2 * HID];
    float h = hprev[idx];
    float r = 1.f / (1.f + __expf(-(ir + hr)));
    float z = 1.f / (1.f + __expf(-(iz + hz)));
    float n = tanhf(in_ + r * hn);
    float hnew = (1.f - z) * n + z * h;
    hout[idx] = hnew;
    if (hstore) hstore[idx] = hnew;
}

// ---------------- final projection: f = h2 @ W1^T + b1 ----------------
__global__ void feats_kernel(const float* __restrict__ h2,
                             const float* __restrict__ W1,
                             const float* __restrict__ b1) {
    __shared__ float hrow[HID];
    int b = blockIdx.x;
    for (int i = threadIdx.x; i < HID; i += blockDim.x)
        hrow[i] = h2[(size_t)b * HID + i];
    __syncthreads();
    int o = threadIdx.x;
    if (o < FEAT) {
        float s = b1[o];
        const float* w = W1 + (size_t)o * HID;
#pragma unroll 8
        for (int k = 0; k < HID; k++) s += hrow[k] * w[k];
        g_feat[(size_t)b * FEAT + o] = s;
    }
}

// ---------------- pairwise sq-dist, stored DIAGONAL-MAJOR ----------------
__global__ void pairdist_kernel() {
    __shared__ float s1[32][31];
    __shared__ float s2[32][31];
    int tid = threadIdx.y * 32 + threadIdx.x;
    int i0 = blockIdx.y * 32, j0 = blockIdx.x * 32;
    for (int idx = tid; idx < 32 * FEAT; idx += 1024) {
        int r = idx / FEAT, c = idx % FEAT;
        s1[r][c] = g_feat[(size_t)(i0 + r) * FEAT + c];
        s2[r][c] = g_feat[(size_t)(NW + j0 + r) * FEAT + c];
    }
    __syncthreads();
    int i = i0 + threadIdx.y, j = j0 + threadIdx.x;
    float d = 0.f;
#pragma unroll
    for (int c = 0; c < FEAT; c++) {
        float t = s1[threadIdx.y][c] - s2[threadIdx.x][c];
        d += t * t;
    }
    g_Dd[(size_t)(i + j) * NW + i] = d;   // coalesced anti-diagonal reads later
}

// ---------------- soft-DTW: single-CTA anti-diagonal wavefront ----------------
__global__ void __launch_bounds__(1024)
softdtw_kernel(float* __restrict__ out) {
    __shared__ float buf[3][NW];
    int tid = threadIdx.x;
    for (int i = tid; i < NW; i += 1024) {
        buf[0][i] = INF_V; buf[1][i] = INF_V; buf[2][i] = INF_V;
    }
    __syncthreads();
    int i2 = 0, i1 = 1, ic = 2;
    const int ND = 2 * NW - 1;   // 4095
    for (int k = 0; k < ND; k++) {
        int lo = k - (NW - 1); if (lo < 0) lo = 0;
        int hi = (k < NW - 1) ? k : (NW - 1);
        const float* A2 = buf[i2];
        const float* A1 = buf[i1];
        float* AC = buf[ic];
        for (int i = lo + tid; i <= hi; i += 1024) {
            float d  = g_Dd[(size_t)k * NW + i];
            float dg = (i == 0) ? ((k == 0) ? 0.f : INF_V) : A2[i - 1];
            float up = (i == 0) ? INF_V : A1[i - 1];
            float lf = A1[i];
            float mn = fminf(dg, fminf(up, lf));
            float s  = __expf(mn - dg) + __expf(mn - up) + __expf(mn - lf);
            float v  = d + mn - __logf(s);
            AC[i] = v;
            if (k == ND - 1 && i == NW - 1) out[0] = v;
        }
        __syncthreads();
        int t = i2; i2 = i1; i1 = ic; ic = t;
    }
}

// ---------------- host orchestration ----------------
extern "C" void kernel_launch(void* const* d_in, const int* in_sizes, int n_in,
                              void* d_out, int out_size) {
    const float* x    = (const float*)d_in[0];
    const float* y    = (const float*)d_in[1];
    const float* Wih1 = (const float*)d_in[2];
    const float* Whh1 = (const float*)d_in[3];
    const float* bih1 = (const float*)d_in[4];
    const float* bhh1 = (const float*)d_in[5];
    const float* Wih2 = (const float*)d_in[6];
    const float* Whh2 = (const float*)d_in[7];
    const float* bih2 = (const float*)d_in[8];
    const float* bhh2 = (const float*)d_in[9];
    const float* W1   = (const float*)d_in[10];
    const float* b1   = (const float*)d_in[11];
    float* out = (float*)d_out;

    float *seq, *gi, *gh, *h1all, *hA, *hB, *hz;
    cudaGetSymbolAddress((void**)&seq,   g_seq);
    cudaGetSymbolAddress((void**)&gi,    g_gi);
    cudaGetSymbolAddress((void**)&gh,    g_gh);
    cudaGetSymbolAddress((void**)&h1all, g_h1all);
    cudaGetSymbolAddress((void**)&hA,    g_hA);
    cudaGetSymbolAddress((void**)&hB,    g_hB);
    cudaGetSymbolAddress((void**)&hz,    g_hz);

    // 1) windows + h0 zeros
    {
        int total = STEPS * BATCH * IN_F;
        build_seq_kernel<<<(total + 255) / 256, 256>>>(x, y);
        zero_kernel<<<(BATCH * HID + 255) / 256, 256>>>(hz, BATCH * HID);
    }

    // 2) layer-1 input gates for all steps at once: (8*4096,384) = seq @ Wih1^T
    sgemm_tn<128, 128, 8, 8, 8><<<dim3(G3 / 128, (STEPS * BATCH) / 128), 256>>>(
        seq, Wih1, bih1, gi, STEPS * BATCH, G3, IN_F);

    // 3) layer-1 recurrence
    {
        const float* hcur = hz;
        float* bufs[2] = {hB, hA};
        for (int s = 0; s < STEPS; s++) {
            sgemm_tn<64, 128, 8, 4, 8><<<dim3(G3 / 128, BATCH / 64), 256>>>(
                hcur, Whh1, bhh1, gh, BATCH, G3, HID);
            float* hout = bufs[s & 1];
            gru_combine_kernel<<<(BATCH * HID + 255) / 256, 256>>>(
                gi + (size_t)s * BATCH * G3, hcur, hout,
                h1all + (size_t)s * BATCH * HID);
            hcur = hout;
        }
    }

    // 4) layer-2 input gates for all steps: h1all @ Wih2^T
    sgemm_tn<128, 128, 8, 8, 8><<<dim3(G3 / 128, (STEPS * BATCH) / 128), 256>>>(
        h1all, Wih2, bih2, gi, STEPS * BATCH, G3, HID);

    // 5) layer-2 recurrence
    const float* h2final;
    {
        const float* hcur = hz;
        float* bufs[2] = {hB, hA};
        for (int s = 0; s < STEPS; s++) {
            sgemm_tn<64, 128, 8, 4, 8><<<dim3(G3 / 128, BATCH / 64), 256>>>(
                hcur, Whh2, bhh2, gh, BATCH, G3, HID);
            float* hout = bufs[s & 1];
            gru_combine_kernel<<<(BATCH * HID + 255) / 256, 256>>>(
                gi + (size_t)s * BATCH * G3, hcur, hout, nullptr);
            hcur = hout;
        }
        h2final = hcur;
    }

    // 6) features (4096 x 30)
    feats_kernel<<<BATCH, 32>>>(h2final, W1, b1);

    // 7) pairwise distances (diagonal-major)
    pairdist_kernel<<<dim3(NW / 32, NW / 32), dim3(32, 32)>>>();

    // 8) soft-DTW
    softdtw_kernel<<<1, 1024>>>(out);
}

// round 2
// speedup vs baseline: 2.1291x; 2.1291x over previous
#include <cuda_runtime.h>
#include <math.h>

#define T_LEN   8196
#define WIN     8
#define STRIDE  4
#define NW      2048
#define BATCH   4096      // both sequences fused
#define IN_F    72
#define HID     128
#define G3      384
#define FEAT    30
#define STEPS   8
#define INF_S   1.44269504e10f   // 1e10 * log2(e): DP runs in log2e-scaled domain
#define LOG2E   1.44269504f
#define LN2     0.693147180559945f

// ---------------- static scratch (no allocations allowed) ----------------
__device__ float g_seq  [STEPS * BATCH * IN_F];
__device__ float g_gi   [STEPS * BATCH * G3];     // reused by layer 2
__device__ float g_h1all[STEPS * BATCH * HID];
__device__ float g_h2   [BATCH * HID];
__device__ float g_feat [BATCH * FEAT];
__device__ float g_Dd   [4096 * 2048];            // diagonal-major D (pre-scaled by log2e)
__device__ float g_WhhT1[HID * G3];
__device__ float g_WhhT2[HID * G3];
__device__ float g_row  [64 * NW];                // bottom-row handoff between strips
__device__ int   g_flag [64];                     // per-strip published 16-col chunk count

// ---------------- small PTX helpers ----------------
__device__ __forceinline__ float ex2f(float x) {
    float r; asm("ex2.approx.ftz.f32 %0, %1;" : "=f"(r) : "f"(x)); return r;
}
__device__ __forceinline__ float lg2f(float x) {
    float r; asm("lg2.approx.ftz.f32 %0, %1;" : "=f"(r) : "f"(x)); return r;
}
__device__ __forceinline__ int ldacq(const int* p) {
    int v; asm volatile("ld.acquire.gpu.global.b32 %0, [%1];" : "=r"(v) : "l"(p) : "memory"); return v;
}
__device__ __forceinline__ void redrel(int* p) {
    asm volatile("red.release.gpu.global.add.u32 [%0], %1;" :: "l"(p), "r"(1) : "memory");
}

// ---------------- window extraction ----------------
__global__ void build_seq_kernel(const float* __restrict__ x,
                                 const float* __restrict__ y) {
    int idx = blockIdx.x * blockDim.x + threadIdx.x;
    const int total = STEPS * BATCH * IN_F;
    if (idx >= total) return;
    int f = idx % IN_F;
    int b = (idx / IN_F) % BATCH;
    int s = idx / (IN_F * BATCH);
    const float* src = (b < NW) ? x : y;
    int w = b & (NW - 1);
    int t = w * STRIDE + s;
    g_seq[idx] = src[(size_t)f * T_LEN + t];
}

// ---------------- init: transpose Whh1/Whh2, zero flags ----------------
__global__ void init_kernel(const float* __restrict__ Whh1,
                            const float* __restrict__ Whh2) {
    int idx = blockIdx.x * blockDim.x + threadIdx.x;
    if (idx < HID * G3) {
        int k = idx / G3, n = idx % G3;
        g_WhhT1[idx] = Whh1[(size_t)n * HID + k];
        g_WhhT2[idx] = Whh2[(size_t)n * HID + k];
    }
    if (idx < 64) g_flag[idx] = 0;
}

// ---------------- SGEMM: C[M,N] = A[M,K] @ B[N,K]^T + bias[N] ----------------
template<int BM, int BN, int BK, int TM, int TN>
__global__ void __launch_bounds__((BM/TM)*(BN/TN))
sgemm_tn(const float* __restrict__ A, const float* __restrict__ Bw,
         const float* __restrict__ bias, float* __restrict__ C,
         int M, int N, int K) {
    __shared__ float As[BK][BM];
    __shared__ float Bs[BK][BN];
    const int nThreads = (BM/TM)*(BN/TN);
    const int tid = threadIdx.x;
    const int rb = blockIdx.y * BM;
    const int cb = blockIdx.x * BN;
    const int tx = tid % (BN/TN);
    const int ty = tid / (BN/TN);

    float acc[TM][TN];
#pragma unroll
    for (int i = 0; i < TM; i++)
#pragma unroll
        for (int j = 0; j < TN; j++) acc[i][j] = 0.f;

    for (int k0 = 0; k0 < K; k0 += BK) {
        for (int idx = tid; idx < BM * BK; idx += nThreads) {
            int r = idx / BK, kk = idx % BK;
            As[kk][r] = A[(size_t)(rb + r) * K + k0 + kk];
        }
        for (int idx = tid; idx < BN * BK; idx += nThreads) {
            int r = idx / BK, kk = idx % BK;
            Bs[kk][r] = Bw[(size_t)(cb + r) * K + k0 + kk];
        }
        __syncthreads();
#pragma unroll
        for (int kk = 0; kk < BK; kk++) {
            float ra[TM], rbv[TN];
#pragma unroll
            for (int i = 0; i < TM; i++) ra[i] = As[kk][ty * TM + i];
#pragma unroll
            for (int j = 0; j < TN; j++) rbv[j] = Bs[kk][tx * TN + j];
#pragma unroll
            for (int i = 0; i < TM; i++)
#pragma unroll
                for (int j = 0; j < TN; j++)
                    acc[i][j] += ra[i] * rbv[j];
        }
        __syncthreads();
    }
#pragma unroll
    for (int i = 0; i < TM; i++) {
        int row = rb + ty * TM + i;
#pragma unroll
        for (int j = 0; j < TN; j++) {
            int col = cb + tx * TN + j;
            C[(size_t)row * N + col] = acc[i][j] + bias[col];
        }
    }
}

// ---------------- persistent GRU layer: all 8 steps in one kernel ----------------
// 128 CTAs x 256 threads, each CTA owns 32 batch rows. h lives in smem.
// Thread tile: rows tr*4..tr*4+3 (tr=tid/32), hidden units tc*4..tc*4+3 (tc=tid%32),
// all 3 gates -> combine is fully register-local.
__global__ void __launch_bounds__(256)
gru_layer_kernel(const float* __restrict__ gi,     // [STEPS][BATCH][G3]
                 const float* __restrict__ WhhT,   // [HID][G3]
                 const float* __restrict__ bhh,    // [G3]
                 float* __restrict__ hall,         // [STEPS][BATCH][HID] or null
                 float* __restrict__ hfinal)       // [BATCH][HID] or null
{
    __shared__ float hsm[32][HID];   // [row][k], 16 KB
    const int tid = threadIdx.x;
    const int tr = tid >> 5;          // 0..7
    const int tc = tid & 31;          // 0..31
    const int rb = blockIdx.x * 32;

    for (int m = tid; m < 32 * HID; m += 256) ((float*)hsm)[m] = 0.f;
    __syncthreads();

    float bq[3][4];
#pragma unroll
    for (int g = 0; g < 3; ++g) {
        float4 bb = *(const float4*)&bhh[g * HID + tc * 4];
        bq[g][0] = bb.x; bq[g][1] = bb.y; bq[g][2] = bb.z; bq[g][3] = bb.w;
    }

    const float4* W4 = (const float4*)WhhT;   // row k = 96 float4s

    for (int step = 0; step < STEPS; ++step) {
        float acc[4][3][4];
#pragma unroll
        for (int ii = 0; ii < 4; ++ii)
#pragma unroll
            for (int g = 0; g < 3; ++g)
#pragma unroll
                for (int o = 0; o < 4; ++o) acc[ii][g][o] = 0.f;

#pragma unroll 4
        for (int k = 0; k < HID; ++k) {
            float a[4];
#pragma unroll
            for (int ii = 0; ii < 4; ++ii) a[ii] = hsm[tr * 4 + ii][k];
#pragma unroll
            for (int g = 0; g < 3; ++g) {
                float4 b = __ldg(&W4[k * 96 + g * 32 + tc]);
#pragma unroll
                for (int ii = 0; ii < 4; ++ii) {
                    acc[ii][g][0] += a[ii] * b.x;
                    acc[ii][g][1] += a[ii] * b.y;
                    acc[ii][g][2] += a[ii] * b.z;
                    acc[ii][g][3] += a[ii] * b.w;
                }
            }
        }
        __syncthreads();   // all GEMM reads of hsm done before combine overwrites it

        const size_t rowbase = (size_t)step * BATCH + rb;
#pragma unroll
        for (int ii = 0; ii < 4; ++ii) {
            const int r = tr * 4 + ii;
            const float* gb = gi + (rowbase + r) * G3;
            float4 gr = __ldg((const float4*)(gb + tc * 4));
            float4 gz = __ldg((const float4*)(gb + HID + tc * 4));
            float4 gn = __ldg((const float4*)(gb + 2 * HID + tc * 4));
            float4 ho = *(const float4*)&hsm[r][tc * 4];
            float irv[4] = {gr.x, gr.y, gr.z, gr.w};
            float izv[4] = {gz.x, gz.y, gz.z, gz.w};
            float inv[4] = {gn.x, gn.y, gn.z, gn.w};
            float hv [4] = {ho.x, ho.y, ho.z, ho.w};
            float ov[4];
#pragma unroll
            for (int o = 0; o < 4; ++o) {
                float hr = acc[ii][0][o] + bq[0][o];
                float hz = acc[ii][1][o] + bq[1][o];
                float hn = acc[ii][2][o] + bq[2][o];
                float rg = 1.f / (1.f + __expf(-(irv[o] + hr)));
                float zg = 1.f / (1.f + __expf(-(izv[o] + hz)));
                float ng = tanhf(inv[o] + rg * hn);
                ov[o] = (1.f - zg) * ng + zg * hv[o];
            }
            float4 hn4 = make_float4(ov[0], ov[1], ov[2], ov[3]);
            *(float4*)&hsm[r][tc * 4] = hn4;
            if (hall)
                *(float4*)&hall[(rowbase + r) * HID + tc * 4] = hn4;
            if (hfinal && step == STEPS - 1)
                *(float4*)&hfinal[(size_t)(rb + r) * HID + tc * 4] = hn4;
        }
        __syncthreads();   // hsm updated before next step's GEMM
    }
}

// ---------------- final projection: f = h2 @ W1^T + b1 ----------------
__global__ void feats_kernel(const float* __restrict__ h2,
                             const float* __restrict__ W1,
                             const float* __restrict__ b1) {
    __shared__ float hrow[HID];
    int b = blockIdx.x;
    for (int i = threadIdx.x; i < HID; i += blockDim.x)
        hrow[i] = h2[(size_t)b * HID + i];
    __syncthreads();
    int o = threadIdx.x;
    if (o < FEAT) {
        float s = b1[o];
        const float* w = W1 + (size_t)o * HID;
#pragma unroll 8
        for (int k = 0; k < HID; k++) s += hrow[k] * w[k];
        g_feat[(size_t)b * FEAT + o] = s;
    }
}

// ---------------- pairwise sq-dist, DIAGONAL-MAJOR, pre-scaled by log2e ----------------
__global__ void pairdist_kernel() {
    __shared__ float s1[32][31];
    __shared__ float s2[32][31];
    int tid = threadIdx.y * 32 + threadIdx.x;
    int i0 = blockIdx.y * 32, j0 = blockIdx.x * 32;
    for (int idx = tid; idx < 32 * FEAT; idx += 1024) {
        int r = idx / FEAT, c = idx % FEAT;
        s1[r][c] = g_feat[(size_t)(i0 + r) * FEAT + c];
        s2[r][c] = g_feat[(size_t)(NW + j0 + r) * FEAT + c];
    }
    __syncthreads();
    int i = i0 + threadIdx.y, j = j0 + threadIdx.x;
    float d = 0.f;
#pragma unroll
    for (int c = 0; c < FEAT; c++) {
        float t = s1[threadIdx.y][c] - s2[threadIdx.x][c];
        d += t * t;
    }
    g_Dd[(size_t)(i + j) * NW + i] = d * LOG2E;
}

// ---------------- soft-DTW: 64-warp pipelined wavefront ----------------
// Strip s (CTA s) owns rows [32s, 32s+32). Lane l = row 32s+l. Skewed march:
// at step t lane l computes cell (i, j=t-l). Neighbors come from 2 shfl_up;
// strip boundaries via g_row + acquire/release flag pipeline (16-col chunks).
// Runs in log2(e)-scaled domain: softmin uses raw ex2/lg2, no scaling muls.
__global__ void __launch_bounds__(32)
softdtw_wave(float* __restrict__ out) {
    const int s = blockIdx.x;
    const int lane = threadIdx.x;
    const int i = s * 32 + lane;

    float v1 = INF_S, v2 = INF_S;   // my R'[i][j-1], R'[i][j-2]
    float rb_prev = INF_S;          // rowprev[j-1] for lane 0
    float rpbuf = INF_S;            // 16-col chunk of rowprev (lanes 0..15)

    const float* dp = g_Dd + (size_t)(s * 32) * NW + i;
    float dbuf[4];
#pragma unroll
    for (int q = 0; q < 4; ++q)
        dbuf[q] = __ldg(dp + (size_t)q * NW);

    const float* rowprev = g_row + (size_t)(s - 1) * NW;   // valid when s>0
    float* rowmine = g_row + (size_t)s * NW;
    int flagseen = 0;

    for (int c = 0; c < 130; ++c) {
        const int t0 = c * 16;
        if (s > 0 && t0 < NW) {
            const int need = c + 1;
            if (flagseen < need) {
                while ((flagseen = ldacq(&g_flag[s - 1])) < need) { }
            }
            float x = INF_S;
            if (lane < 16) x = rowprev[t0 + lane];
            rpbuf = x;
        }
#pragma unroll
        for (int q = 0; q < 16; ++q) {
            const int t = t0 + q;
            float u1 = __shfl_up_sync(0xffffffffu, v1, 1);
            float u2 = __shfl_up_sync(0xffffffffu, v2, 1);
            float rbc = __shfl_sync(0xffffffffu, rpbuf, q);
            if (lane == 0) {
                if (s == 0) { u1 = INF_S; u2 = (t == 0) ? 0.f : INF_S; }
                else        { u1 = rbc;   u2 = rb_prev; }
                rb_prev = rbc;
            }
            const int j = t - lane;
            const bool active = (j >= 0) && (j < NW);
            float dval = dbuf[q & 3];
            {   // prefetch D for step t+4 (diag row 32s+t+4, same lane col)
                int kk = s * 32 + t + 4;
                float nd = 0.f;
                if (kk < 4095) nd = __ldg(dp + (size_t)(t + 4) * NW);
                dbuf[q & 3] = nd;
            }
            float mn = fminf(v1, fminf(u1, u2));
            float e  = ex2f(mn - u2) + ex2f(mn - u1) + ex2f(mn - v1);
            float v  = dval + mn - lg2f(e);
            if (active) { v2 = v1; v1 = v; }
            if (lane == 31 && active) {
                if (s < 63) {
                    rowmine[j] = v;
                    if ((j & 15) == 15) redrel(&g_flag[s]);
                } else if (j == NW - 1) {
                    out[0] = v * LN2;
                }
            }
        }
    }
}

// ---------------- host orchestration ----------------
extern "C" void kernel_launch(void* const* d_in, const int* in_sizes, int n_in,
                              void* d_out, int out_size) {
    const float* x    = (const float*)d_in[0];
    const float* y    = (const float*)d_in[1];
    const float* Wih1 = (const float*)d_in[2];
    const float* Whh1 = (const float*)d_in[3];
    const float* bih1 = (const float*)d_in[4];
    const float* bhh1 = (const float*)d_in[5];
    const float* Wih2 = (const float*)d_in[6];
    const float* Whh2 = (const float*)d_in[7];
    const float* bih2 = (const float*)d_in[8];
    const float* bhh2 = (const float*)d_in[9];
    const float* W1   = (const float*)d_in[10];
    const float* b1   = (const float*)d_in[11];
    float* out = (float*)d_out;

    float *seq, *gi, *h1all, *h2, *whT1, *whT2;
    cudaGetSymbolAddress((void**)&seq,   g_seq);
    cudaGetSymbolAddress((void**)&gi,    g_gi);
    cudaGetSymbolAddress((void**)&h1all, g_h1all);
    cudaGetSymbolAddress((void**)&h2,    g_h2);
    cudaGetSymbolAddress((void**)&whT1,  g_WhhT1);
    cudaGetSymbolAddress((void**)&whT2,  g_WhhT2);

    // 1) windows + weight transpose + flag reset
    {
        int total = STEPS * BATCH * IN_F;
        build_seq_kernel<<<(total + 255) / 256, 256>>>(x, y);
        init_kernel<<<(HID * G3 + 255) / 256, 256>>>(Whh1, Whh2);
    }

    // 2) layer-1 input gates for all steps: (8*4096,384) = seq @ Wih1^T  (K=72)
    sgemm_tn<128, 128, 24, 8, 8><<<dim3(G3 / 128, (STEPS * BATCH) / 128), 256>>>(
        seq, Wih1, bih1, gi, STEPS * BATCH, G3, IN_F);

    // 3) layer-1 recurrence (one persistent kernel, 8 steps)
    gru_layer_kernel<<<BATCH / 32, 256>>>(gi, whT1, bhh1, h1all, nullptr);

    // 4) layer-2 input gates: h1all @ Wih2^T  (K=128)
    sgemm_tn<128, 128, 16, 8, 8><<<dim3(G3 / 128, (STEPS * BATCH) / 128), 256>>>(
        h1all, Wih2, bih2, gi, STEPS * BATCH, G3, HID);

    // 5) layer-2 recurrence
    gru_layer_kernel<<<BATCH / 32, 256>>>(gi, whT2, bhh2, nullptr, h2);

    // 6) features (4096 x 30)
    feats_kernel<<<BATCH, 32>>>(h2, W1, b1);

    // 7) pairwise distances (diagonal-major, log2e-scaled)
    pairdist_kernel<<<dim3(NW / 32, NW / 32), dim3(32, 32)>>>();

    // 8) soft-DTW pipelined wavefront
    softdtw_wave<<<64, 32>>>(out);
}

// round 3
// speedup vs baseline: 2.6697x; 1.2539x over previous
#include <cuda_runtime.h>
#include <math.h>

#define T_LEN   8196
#define WIN     8
#define STRIDE  4
#define NW      2048
#define BATCH   4096      // both sequences fused
#define IN_F    72
#define HID     128
#define G3      384
#define FEAT    30
#define STEPS   8
#define INF_S   1.44269504e10f   // 1e10 * log2(e): DP runs in log2e-scaled domain
#define LOG2E   1.44269504f
#define LN2     0.693147180559945f

// ---------------- static scratch (no allocations allowed) ----------------
__device__ float g_seq  [STEPS * BATCH * IN_F];
__device__ float g_gi   [STEPS * BATCH * G3];     // reused by layer 2
__device__ float g_h1all[STEPS * BATCH * HID];
__device__ float g_h2   [BATCH * HID];
__device__ float g_feat [BATCH * FEAT];
__device__ float g_Dd   [4096 * 2048];            // diagonal-major D (pre-scaled by log2e)
__device__ float g_WhhT1[HID * G3];
__device__ float g_WhhT2[HID * G3];
__device__ float g_row  [64 * NW];                // bottom-row handoff between strips
__device__ int   g_flag [64];                     // per-strip published 16-col chunk count

// ---------------- small PTX helpers ----------------
__device__ __forceinline__ float ex2f(float x) {
    float r; asm("ex2.approx.ftz.f32 %0, %1;" : "=f"(r) : "f"(x)); return r;
}
__device__ __forceinline__ float lg2f(float x) {
    float r; asm("lg2.approx.ftz.f32 %0, %1;" : "=f"(r) : "f"(x)); return r;
}
__device__ __forceinline__ int ldacq(const int* p) {
    int v; asm volatile("ld.acquire.gpu.global.b32 %0, [%1];" : "=r"(v) : "l"(p) : "memory"); return v;
}
__device__ __forceinline__ void redrel(int* p) {
    asm volatile("red.release.gpu.global.add.u32 [%0], %1;" :: "l"(p), "r"(1) : "memory");
}

// ---------------- window extraction ----------------
__global__ void build_seq_kernel(const float* __restrict__ x,
                                 const float* __restrict__ y) {
    int idx = blockIdx.x * blockDim.x + threadIdx.x;
    const int total = STEPS * BATCH * IN_F;
    if (idx >= total) return;
    int f = idx % IN_F;
    int b = (idx / IN_F) % BATCH;
    int s = idx / (IN_F * BATCH);
    const float* src = (b < NW) ? x : y;
    int w = b & (NW - 1);
    int t = w * STRIDE + s;
    g_seq[idx] = src[(size_t)f * T_LEN + t];
}

// ---------------- init: transpose Whh1/Whh2, zero flags ----------------
__global__ void init_kernel(const float* __restrict__ Whh1,
                            const float* __restrict__ Whh2) {
    int idx = blockIdx.x * blockDim.x + threadIdx.x;
    if (idx < HID * G3) {
        int k = idx / G3, n = idx % G3;
        g_WhhT1[idx] = Whh1[(size_t)n * HID + k];
        g_WhhT2[idx] = Whh2[(size_t)n * HID + k];
    }
    if (idx < 64) g_flag[idx] = 0;
}

// ---------------- SGEMM (double-buffered): C = A[M,K] @ B[N,K]^T + bias ----------------
// BM=BN=128, 256 threads, 8x8 thread tile, float4 loads, padded smem.
template<int BM, int BN, int BK, int TM, int TN>
__global__ void __launch_bounds__(256)
sgemm_db(const float* __restrict__ A, const float* __restrict__ Bw,
         const float* __restrict__ bias, float* __restrict__ C,
         int M, int N, int K) {
    constexpr int THREADS = (BM / TM) * (BN / TN);        // 256
    constexpr int PAD = 4;
    constexpr int C4S = BK / 4;                           // float4 per k-row
    constexpr int NL  = (BM * BK / 4) / THREADS;          // float4 loads per thread

    __shared__ float As[2][BK][BM + PAD];
    __shared__ float Bs[2][BK][BN + PAD];

    const int tid = threadIdx.x;
    const int rb = blockIdx.y * BM;
    const int cb = blockIdx.x * BN;
    const int tx = tid % (BN / TN);
    const int ty = tid / (BN / TN);

    const int nt = K / BK;

    float4 aR[NL], bR[NL];
    int lrow[NL], lcc[NL];
#pragma unroll
    for (int i = 0; i < NL; ++i) {
        int idx = tid + i * THREADS;
        lrow[i] = idx / C4S;
        lcc[i]  = idx % C4S;
    }

    auto loadT = [&](int t) {
#pragma unroll
        for (int i = 0; i < NL; ++i) {
            aR[i] = *(const float4*)&A[(size_t)(rb + lrow[i]) * K + t * BK + lcc[i] * 4];
            bR[i] = *(const float4*)&Bw[(size_t)(cb + lrow[i]) * K + t * BK + lcc[i] * 4];
        }
    };
    auto storeT = [&](int buf) {
#pragma unroll
        for (int i = 0; i < NL; ++i) {
            As[buf][lcc[i] * 4 + 0][lrow[i]] = aR[i].x;
            As[buf][lcc[i] * 4 + 1][lrow[i]] = aR[i].y;
            As[buf][lcc[i] * 4 + 2][lrow[i]] = aR[i].z;
            As[buf][lcc[i] * 4 + 3][lrow[i]] = aR[i].w;
            Bs[buf][lcc[i] * 4 + 0][lrow[i]] = bR[i].x;
            Bs[buf][lcc[i] * 4 + 1][lrow[i]] = bR[i].y;
            Bs[buf][lcc[i] * 4 + 2][lrow[i]] = bR[i].z;
            Bs[buf][lcc[i] * 4 + 3][lrow[i]] = bR[i].w;
        }
    };

    float acc[TM][TN];
#pragma unroll
    for (int i = 0; i < TM; i++)
#pragma unroll
        for (int j = 0; j < TN; j++) acc[i][j] = 0.f;

    loadT(0);
    storeT(0);
    __syncthreads();

    for (int t = 0; t < nt; ++t) {
        const int cur = t & 1;
        if (t + 1 < nt) loadT(t + 1);
#pragma unroll
        for (int kk = 0; kk < BK; ++kk) {
            float4 a0 = *(const float4*)&As[cur][kk][ty * TM];
            float4 a1 = *(const float4*)&As[cur][kk][ty * TM + 4];
            float4 b0 = *(const float4*)&Bs[cur][kk][tx * TN];
            float4 b1 = *(const float4*)&Bs[cur][kk][tx * TN + 4];
            float ra[8]  = {a0.x, a0.y, a0.z, a0.w, a1.x, a1.y, a1.z, a1.w};
            float rbv[8] = {b0.x, b0.y, b0.z, b0.w, b1.x, b1.y, b1.z, b1.w};
#pragma unroll
            for (int i = 0; i < TM; i++)
#pragma unroll
                for (int j = 0; j < TN; j++)
                    acc[i][j] += ra[i] * rbv[j];
        }
        if (t + 1 < nt) storeT((t + 1) & 1);
        __syncthreads();
    }

    float bv[TN];
#pragma unroll
    for (int j = 0; j < TN; j++) bv[j] = bias[cb + tx * TN + j];
#pragma unroll
    for (int i = 0; i < TM; i++) {
        int row = rb + ty * TM + i;
        float4 o0 = make_float4(acc[i][0] + bv[0], acc[i][1] + bv[1],
                                acc[i][2] + bv[2], acc[i][3] + bv[3]);
        float4 o1 = make_float4(acc[i][4] + bv[4], acc[i][5] + bv[5],
                                acc[i][6] + bv[6], acc[i][7] + bv[7]);
        *(float4*)&C[(size_t)row * N + cb + tx * TN]     = o0;
        *(float4*)&C[(size_t)row * N + cb + tx * TN + 4] = o1;
    }
}

// ---------------- persistent GRU layer: split-K across 2 warp groups ----------------
// 128 CTAs x 512 threads. CTA owns 32 batch rows; h in smem.
// Group kh=tid/256 accumulates k in [kh*64, kh*64+64). Partials exchanged via smem,
// combine split: group0/tr<4 does rows 0-15, group1/tr>=4 does rows 16-31.
__global__ void __launch_bounds__(512)
gru_layer_kernel(const float* __restrict__ gi,     // [STEPS][BATCH][G3]
                 const float4* __restrict__ W4,    // [HID][G3] as float4
                 const float* __restrict__ bhh,    // [G3]
                 float* __restrict__ hall,         // [STEPS][BATCH][HID] or null
                 float* __restrict__ hfinal)       // [BATCH][HID] or null
{
    extern __shared__ float sraw[];
    float (*hsm)[HID] = (float (*)[HID])sraw;                 // 32x128 = 16KB
    float (*psum)[G3] = (float (*)[G3])(sraw + 32 * HID);     // 32x384 = 48KB

    const int tid = threadIdx.x;
    const int kh  = tid >> 8;          // 0 or 1
    const int gt  = tid & 255;
    const int tr  = gt >> 5;           // 0..7
    const int tc  = gt & 31;           // 0..31
    const int rb  = blockIdx.x * 32;
    const int kbase = kh * 64;
    const bool comb = (kh == 0) ? (tr < 4) : (tr >= 4);

    for (int m = tid; m < 32 * HID; m += 512) sraw[m] = 0.f;
    __syncthreads();

    float bq[3][4];
#pragma unroll
    for (int g = 0; g < 3; ++g) {
        float4 bb = *(const float4*)&bhh[g * HID + tc * 4];
        bq[g][0] = bb.x; bq[g][1] = bb.y; bq[g][2] = bb.z; bq[g][3] = bb.w;
    }

    for (int step = 0; step < STEPS; ++step) {
        float acc[4][3][4];
#pragma unroll
        for (int ii = 0; ii < 4; ++ii)
#pragma unroll
            for (int g = 0; g < 3; ++g)
#pragma unroll
                for (int o = 0; o < 4; ++o) acc[ii][g][o] = 0.f;

#pragma unroll 4
        for (int kk = 0; kk < 64; ++kk) {
            const int k = kbase + kk;
            float a[4];
#pragma unroll
            for (int ii = 0; ii < 4; ++ii) a[ii] = hsm[tr * 4 + ii][k];
#pragma unroll
            for (int g = 0; g < 3; ++g) {
                float4 b = __ldg(&W4[k * 96 + g * 32 + tc]);
#pragma unroll
                for (int ii = 0; ii < 4; ++ii) {
                    acc[ii][g][0] += a[ii] * b.x;
                    acc[ii][g][1] += a[ii] * b.y;
                    acc[ii][g][2] += a[ii] * b.z;
                    acc[ii][g][3] += a[ii] * b.w;
                }
            }
        }
        __syncthreads();   // all hsm reads done

        if (!comb) {       // this half publishes its partials
#pragma unroll
            for (int ii = 0; ii < 4; ++ii) {
                const int r = tr * 4 + ii;
#pragma unroll
                for (int g = 0; g < 3; ++g)
                    *(float4*)&psum[r][g * HID + tc * 4] =
                        make_float4(acc[ii][g][0], acc[ii][g][1],
                                    acc[ii][g][2], acc[ii][g][3]);
            }
        }
        __syncthreads();

        if (comb) {
            const size_t rowbase = (size_t)step * BATCH + rb;
#pragma unroll
            for (int ii = 0; ii < 4; ++ii) {
                const int r = tr * 4 + ii;
                const float* gb = gi + (rowbase + r) * G3;
                float4 gr = __ldg((const float4*)(gb + tc * 4));
                float4 gz = __ldg((const float4*)(gb + HID + tc * 4));
                float4 gn = __ldg((const float4*)(gb + 2 * HID + tc * 4));
                float4 p0 = *(const float4*)&psum[r][0 * HID + tc * 4];
                float4 p1 = *(const float4*)&psum[r][1 * HID + tc * 4];
                float4 p2 = *(const float4*)&psum[r][2 * HID + tc * 4];
                float4 ho = *(const float4*)&hsm[r][tc * 4];
                float irv[4] = {gr.x, gr.y, gr.z, gr.w};
                float izv[4] = {gz.x, gz.y, gz.z, gz.w};
                float inv[4] = {gn.x, gn.y, gn.z, gn.w};
                float hv [4] = {ho.x, ho.y, ho.z, ho.w};
                float pr [4] = {p0.x, p0.y, p0.z, p0.w};
                float pz [4] = {p1.x, p1.y, p1.z, p1.w};
                float pn [4] = {p2.x, p2.y, p2.z, p2.w};
                float ov[4];
#pragma unroll
                for (int o = 0; o < 4; ++o) {
                    float hr = acc[ii][0][o] + pr[o] + bq[0][o];
                    float hz = acc[ii][1][o] + pz[o] + bq[1][o];
                    float hn = acc[ii][2][o] + pn[o] + bq[2][o];
                    float rg = 1.f / (1.f + __expf(-(irv[o] + hr)));
                    float zg = 1.f / (1.f + __expf(-(izv[o] + hz)));
                    float ng = tanhf(inv[o] + rg * hn);
                    ov[o] = (1.f - zg) * ng + zg * hv[o];
                }
                float4 hn4 = make_float4(ov[0], ov[1], ov[2], ov[3]);
                *(float4*)&hsm[r][tc * 4] = hn4;
                if (hall)
                    *(float4*)&hall[(rowbase + r) * HID + tc * 4] = hn4;
                if (hfinal && step == STEPS - 1)
                    *(float4*)&hfinal[(size_t)(rb + r) * HID + tc * 4] = hn4;
            }
        }
        __syncthreads();   // hsm updated before next step's GEMM
    }
}

// ---------------- final projection: f = h2 @ W1^T + b1 ----------------
__global__ void feats_kernel(const float* __restrict__ h2,
                             const float* __restrict__ W1,
                             const float* __restrict__ b1) {
    __shared__ float hrow[HID];
    int b = blockIdx.x;
    for (int i = threadIdx.x; i < HID; i += blockDim.x)
        hrow[i] = h2[(size_t)b * HID + i];
    __syncthreads();
    int o = threadIdx.x;
    if (o < FEAT) {
        float s = b1[o];
        const float* w = W1 + (size_t)o * HID;
#pragma unroll 8
        for (int k = 0; k < HID; k++) s += hrow[k] * w[k];
        g_feat[(size_t)b * FEAT + o] = s;
    }
}

// ---------------- pairwise sq-dist, DIAGONAL-MAJOR, pre-scaled by log2e ----------------
__global__ void pairdist_kernel() {
    __shared__ float s1[32][31];
    __shared__ float s2[32][31];
    int tid = threadIdx.y * 32 + threadIdx.x;
    int i0 = blockIdx.y * 32, j0 = blockIdx.x * 32;
    for (int idx = tid; idx < 32 * FEAT; idx += 1024) {
        int r = idx / FEAT, c = idx % FEAT;
        s1[r][c] = g_feat[(size_t)(i0 + r) * FEAT + c];
        s2[r][c] = g_feat[(size_t)(NW + j0 + r) * FEAT + c];
    }
    __syncthreads();
    int i = i0 + threadIdx.y, j = j0 + threadIdx.x;
    float d = 0.f;
#pragma unroll
    for (int c = 0; c < FEAT; c++) {
        float t = s1[threadIdx.y][c] - s2[threadIdx.x][c];
        d += t * t;
    }
    g_Dd[(size_t)(i + j) * NW + i] = d * LOG2E;
}

// ---------------- soft-DTW: 64-warp pipelined wavefront ----------------
__global__ void __launch_bounds__(32)
softdtw_wave(float* __restrict__ out) {
    const int s = blockIdx.x;
    const int lane = threadIdx.x;
    const int i = s * 32 + lane;

    float v1 = INF_S, v2 = INF_S;   // my R'[i][j-1], R'[i][j-2]
    float rb_prev = INF_S;          // rowprev[j-1] for lane 0
    float rpbuf = INF_S;            // 16-col chunk of rowprev (lanes 0..15)

    const float* dp = g_Dd + (size_t)(s * 32) * NW + i;
    float dbuf[4];
#pragma unroll
    for (int q = 0; q < 4; ++q)
        dbuf[q] = __ldg(dp + (size_t)q * NW);

    const float* rowprev = g_row + (size_t)(s - 1) * NW;   // valid when s>0
    float* rowmine = g_row + (size_t)s * NW;
    int flagseen = 0;

    for (int c = 0; c < 130; ++c) {
        const int t0 = c * 16;
        if (s > 0 && t0 < NW) {
            const int need = c + 1;
            if (flagseen < need) {
                while ((flagseen = ldacq(&g_flag[s - 1])) < need) { }
            }
            float x = INF_S;
            if (lane < 16) x = rowprev[t0 + lane];
            rpbuf = x;
        }
#pragma unroll
        for (int q = 0; q < 16; ++q) {
            const int t = t0 + q;
            float u1 = __shfl_up_sync(0xffffffffu, v1, 1);
            float u2 = __shfl_up_sync(0xffffffffu, v2, 1);
            float rbc = __shfl_sync(0xffffffffu, rpbuf, q);
            if (lane == 0) {
                if (s == 0) { u1 = INF_S; u2 = (t == 0) ? 0.f : INF_S; }
                else        { u1 = rbc;   u2 = rb_prev; }
                rb_prev = rbc;
            }
            const int j = t - lane;
            const bool active = (j >= 0) && (j < NW);
            float dval = dbuf[q & 3];
            {   // prefetch D for step t+4
                int kk = s * 32 + t + 4;
                float nd = 0.f;
                if (kk < 4095) nd = __ldg(dp + (size_t)(t + 4) * NW);
                dbuf[q & 3] = nd;
            }
            float mn = fminf(v1, fminf(u1, u2));
            float e  = ex2f(mn - u2) + ex2f(mn - u1) + ex2f(mn - v1);
            float v  = dval + mn - lg2f(e);
            if (active) { v2 = v1; v1 = v; }
            if (lane == 31 && active) {
                if (s < 63) {
                    rowmine[j] = v;
                    if ((j & 15) == 15) redrel(&g_flag[s]);
                } else if (j == NW - 1) {
                    out[0] = v * LN2;
                }
            }
        }
    }
}

// ---------------- host orchestration ----------------
extern "C" void kernel_launch(void* const* d_in, const int* in_sizes, int n_in,
                              void* d_out, int out_size) {
    const float* x    = (const float*)d_in[0];
    const float* y    = (const float*)d_in[1];
    const float* Wih1 = (const float*)d_in[2];
    const float* Whh1 = (const float*)d_in[3];
    const float* bih1 = (const float*)d_in[4];
    const float* bhh1 = (const float*)d_in[5];
    const float* Wih2 = (const float*)d_in[6];
    const float* Whh2 = (const float*)d_in[7];
    const float* bih2 = (const float*)d_in[8];
    const float* bhh2 = (const float*)d_in[9];
    const float* W1   = (const float*)d_in[10];
    const float* b1   = (const float*)d_in[11];
    float* out = (float*)d_out;

    float *seq, *gi, *h1all, *h2, *whT1, *whT2;
    cudaGetSymbolAddress((void**)&seq,   g_seq);
    cudaGetSymbolAddress((void**)&gi,    g_gi);
    cudaGetSymbolAddress((void**)&h1all, g_h1all);
    cudaGetSymbolAddress((void**)&h2,    g_h2);
    cudaGetSymbolAddress((void**)&whT1,  g_WhhT1);
    cudaGetSymbolAddress((void**)&whT2,  g_WhhT2);

    const int GRU_SMEM = (32 * HID + 32 * G3) * 4;   // 64 KB
    cudaFuncSetAttribute(gru_layer_kernel,
                         cudaFuncAttributeMaxDynamicSharedMemorySize, GRU_SMEM);

    // 1) windows + weight transpose + flag reset
    {
        int total = STEPS * BATCH * IN_F;
        build_seq_kernel<<<(total + 255) / 256, 256>>>(x, y);
        init_kernel<<<(HID * G3 + 255) / 256, 256>>>(Whh1, Whh2);
    }

    // 2) layer-1 input gates for all steps: (8*4096,384) = seq @ Wih1^T  (K=72)
    sgemm_db<128, 128, 8, 8, 8><<<dim3(G3 / 128, (STEPS * BATCH) / 128), 256>>>(
        seq, Wih1, bih1, gi, STEPS * BATCH, G3, IN_F);

    // 3) layer-1 recurrence (one persistent kernel, 8 steps)
    gru_layer_kernel<<<BATCH / 32, 512, GRU_SMEM>>>(
        gi, (const float4*)whT1, bhh1, h1all, nullptr);

    // 4) layer-2 input gates: h1all @ Wih2^T  (K=128)
    sgemm_db<128, 128, 16, 8, 8><<<dim3(G3 / 128, (STEPS * BATCH) / 128), 256>>>(
        h1all, Wih2, bih2, gi, STEPS * BATCH, G3, HID);

    // 5) layer-2 recurrence
    gru_layer_kernel<<<BATCH / 32, 512, GRU_SMEM>>>(
        gi, (const float4*)whT2, bhh2, nullptr, h2);

    // 6) features (4096 x 30)
    feats_kernel<<<BATCH, 32>>>(h2, W1, b1);

    // 7) pairwise distances (diagonal-major, log2e-scaled)
    pairdist_kernel<<<dim3(NW / 32, NW / 32), dim3(32, 32)>>>();

    // 8) soft-DTW pipelined wavefront
    softdtw_wave<<<64, 32>>>(out);
}

// round 4
// speedup vs baseline: 3.0114x; 1.1280x over previous
#include <cuda_runtime.h>
#include <math.h>

#define T_LEN   8196
#define WIN     8
#define STRIDE  4
#define NW      2048
#define BATCH   4096
#define IN_F    72
#define HID     128
#define G3      384
#define FEAT    30
#define STEPS   8
#define INF_S   1.44269504e10f   // 1e10 * log2(e): DP runs in log2e-scaled domain
#define LOG2E   1.44269504f
#define LN2     0.693147180559945f

// ---------------- static scratch ----------------
__device__ float g_seq  [STEPS * BATCH * IN_F];
__device__ float g_gi   [STEPS * BATCH * G3];
__device__ float g_h1all[STEPS * BATCH * HID];
__device__ float g_feat [BATCH * FEAT];
__device__ float g_Dd   [4224 * 2048];            // diag-major D (padded rows for prefetch)
__device__ float g_WhhT1[HID * G3];
__device__ float g_WhhT2[HID * G3];
__device__ float g_row  [64 * NW];
__device__ int   g_flag [64];

// ---------------- PTX helpers ----------------
__device__ __forceinline__ float ex2f(float x) {
    float r; asm("ex2.approx.ftz.f32 %0, %1;" : "=f"(r) : "f"(x)); return r;
}
__device__ __forceinline__ float lg2f(float x) {
    float r; asm("lg2.approx.ftz.f32 %0, %1;" : "=f"(r) : "f"(x)); return r;
}
__device__ __forceinline__ int ldacq(const int* p) {
    int v; asm volatile("ld.acquire.gpu.global.b32 %0, [%1];" : "=r"(v) : "l"(p) : "memory"); return v;
}
__device__ __forceinline__ void stg_pred(float* p, float v, int pred) {
    asm volatile("{\n\t.reg .pred p;\n\tsetp.ne.s32 p, %0, 0;\n\t@p st.global.f32 [%1], %2;\n\t}"
                 :: "r"(pred), "l"(p), "f"(v) : "memory");
}
__device__ __forceinline__ void red_rel_pred(int* p, int pred) {
    asm volatile("{\n\t.reg .pred p;\n\tsetp.ne.s32 p, %0, 0;\n\t@p red.release.gpu.global.add.u32 [%1], 1;\n\t}"
                 :: "r"(pred), "l"(p) : "memory");
}

// ---------------- prep: windows + weight transpose + flag reset ----------------
__global__ void prep_kernel(const float* __restrict__ x, const float* __restrict__ y,
                            const float* __restrict__ Whh1, const float* __restrict__ Whh2) {
    int idx = blockIdx.x * blockDim.x + threadIdx.x;
    const int total = STEPS * BATCH * IN_F;
    if (idx < total) {
        int f = idx % IN_F;
        int b = (idx / IN_F) % BATCH;
        int s = idx / (IN_F * BATCH);
        const float* src = (b < NW) ? x : y;
        int w = b & (NW - 1);
        g_seq[idx] = src[(size_t)f * T_LEN + w * STRIDE + s];
    }
    if (idx < HID * G3) {
        int k = idx / G3, n = idx % G3;
        g_WhhT1[idx] = Whh1[(size_t)n * HID + k];
        g_WhhT2[idx] = Whh2[(size_t)n * HID + k];
    }
    if (idx < 64) g_flag[idx] = 0;
}

// ---------------- SGEMM (double-buffered, warp-tiled): C = A@B^T + bias ----------------
template<int BK>
__global__ void __launch_bounds__(256)
sgemm_db(const float* __restrict__ A, const float* __restrict__ Bw,
         const float* __restrict__ bias, float* __restrict__ C,
         int M, int N, int K) {
    constexpr int BM = 128, BN = 128;
    constexpr int PAD = 4;
    constexpr int C4S = BK / 4;
    constexpr int NL  = (BM * BK / 4) / 256;

    __shared__ float As[2][BK][BM + PAD];
    __shared__ float Bs[2][BK][BN + PAD];

    const int tid = threadIdx.x;
    const int rb = blockIdx.y * BM;
    const int cb = blockIdx.x * BN;
    const int warp = tid >> 5, lane = tid & 31;
    const int wr = (warp & 3) * 32;       // warp row origin (4 warp-rows)
    const int wc = (warp >> 2) * 64;      // warp col origin (2 warp-cols)
    const int lr = ((lane >> 3) & 3) * 8; // lane row in warp tile
    const int lc = (lane & 7) * 8;        // lane col in warp tile

    const int nt = K / BK;

    float4 aR[NL], bR[NL];
    int lrow[NL], lcc[NL];
#pragma unroll
    for (int i = 0; i < NL; ++i) {
        int idx = tid + i * 256;
        lrow[i] = idx / C4S;
        lcc[i]  = idx % C4S;
    }

    auto loadT = [&](int t) {
#pragma unroll
        for (int i = 0; i < NL; ++i) {
            aR[i] = *(const float4*)&A[(size_t)(rb + lrow[i]) * K + t * BK + lcc[i] * 4];
            bR[i] = *(const float4*)&Bw[(size_t)(cb + lrow[i]) * K + t * BK + lcc[i] * 4];
        }
    };
    auto storeT = [&](int buf) {
#pragma unroll
        for (int i = 0; i < NL; ++i) {
            As[buf][lcc[i] * 4 + 0][lrow[i]] = aR[i].x;
            As[buf][lcc[i] * 4 + 1][lrow[i]] = aR[i].y;
            As[buf][lcc[i] * 4 + 2][lrow[i]] = aR[i].z;
            As[buf][lcc[i] * 4 + 3][lrow[i]] = aR[i].w;
            Bs[buf][lcc[i] * 4 + 0][lrow[i]] = bR[i].x;
            Bs[buf][lcc[i] * 4 + 1][lrow[i]] = bR[i].y;
            Bs[buf][lcc[i] * 4 + 2][lrow[i]] = bR[i].z;
            Bs[buf][lcc[i] * 4 + 3][lrow[i]] = bR[i].w;
        }
    };

    float acc[8][8];
#pragma unroll
    for (int i = 0; i < 8; i++)
#pragma unroll
        for (int j = 0; j < 8; j++) acc[i][j] = 0.f;

    loadT(0);
    storeT(0);
    __syncthreads();

    for (int t = 0; t < nt; ++t) {
        const int cur = t & 1;
        if (t + 1 < nt) loadT(t + 1);
#pragma unroll
        for (int kk = 0; kk < BK; ++kk) {
            float4 a0 = *(const float4*)&As[cur][kk][wr + lr];
            float4 a1 = *(const float4*)&As[cur][kk][wr + lr + 4];
            float4 b0 = *(const float4*)&Bs[cur][kk][wc + lc];
            float4 b1 = *(const float4*)&Bs[cur][kk][wc + lc + 4];
            float ra[8]  = {a0.x, a0.y, a0.z, a0.w, a1.x, a1.y, a1.z, a1.w};
            float rbv[8] = {b0.x, b0.y, b0.z, b0.w, b1.x, b1.y, b1.z, b1.w};
#pragma unroll
            for (int i = 0; i < 8; i++)
#pragma unroll
                for (int j = 0; j < 8; j++)
                    acc[i][j] += ra[i] * rbv[j];
        }
        if (t + 1 < nt) storeT((t + 1) & 1);
        __syncthreads();
    }

    float bv[8];
#pragma unroll
    for (int j = 0; j < 8; j++) bv[j] = bias[cb + wc + lc + j];
#pragma unroll
    for (int i = 0; i < 8; i++) {
        int row = rb + wr + lr + i;
        float4 o0 = make_float4(acc[i][0] + bv[0], acc[i][1] + bv[1],
                                acc[i][2] + bv[2], acc[i][3] + bv[3]);
        float4 o1 = make_float4(acc[i][4] + bv[4], acc[i][5] + bv[5],
                                acc[i][6] + bv[6], acc[i][7] + bv[7]);
        *(float4*)&C[(size_t)row * N + cb + wc + lc]     = o0;
        *(float4*)&C[(size_t)row * N + cb + wc + lc + 4] = o1;
    }
}

// ---------------- persistent GRU layer (split-K, pipelined k-loop, optional feats) ----------------
__global__ void __launch_bounds__(512)
gru_layer_kernel(const float* __restrict__ gi,
                 const float4* __restrict__ W4,    // [HID][G3] as float4
                 const float* __restrict__ bhh,
                 float* __restrict__ hall,         // [STEPS][BATCH][HID] or null
                 const float* __restrict__ W1,     // if non-null: compute feats at end
                 const float* __restrict__ b1)
{
    extern __shared__ float sraw[];
    float (*hsm)[HID] = (float (*)[HID])sraw;                 // 32x128
    float (*psum)[G3] = (float (*)[G3])(sraw + 32 * HID);     // 32x384

    const int tid = threadIdx.x;
    const int kh  = tid >> 8;
    const int gt  = tid & 255;
    const int tr  = gt >> 5;
    const int tc  = gt & 31;
    const int rb  = blockIdx.x * 32;
    const int kbase = kh * 64;
    const bool comb = (kh == 0) ? (tr < 4) : (tr >= 4);

    for (int m = tid; m < 32 * HID; m += 512) sraw[m] = 0.f;
    __syncthreads();

    float bq[3][4];
#pragma unroll
    for (int g = 0; g < 3; ++g) {
        float4 bb = *(const float4*)&bhh[g * HID + tc * 4];
        bq[g][0] = bb.x; bq[g][1] = bb.y; bq[g][2] = bb.z; bq[g][3] = bb.w;
    }

    for (int step = 0; step < STEPS; ++step) {
        float acc[4][3][4];
#pragma unroll
        for (int ii = 0; ii < 4; ++ii)
#pragma unroll
            for (int g = 0; g < 3; ++g)
#pragma unroll
                for (int o = 0; o < 4; ++o) acc[ii][g][o] = 0.f;

        // software-pipelined k loop
        float4 bc[3]; float ac[4];
#pragma unroll
        for (int g = 0; g < 3; ++g) bc[g] = __ldg(&W4[kbase * 96 + g * 32 + tc]);
#pragma unroll
        for (int ii = 0; ii < 4; ++ii) ac[ii] = hsm[tr * 4 + ii][kbase];

#pragma unroll 2
        for (int kk = 0; kk < 64; ++kk) {
            const int kn = kbase + ((kk + 1) & 63);
            float4 bn[3]; float an[4];
#pragma unroll
            for (int g = 0; g < 3; ++g) bn[g] = __ldg(&W4[kn * 96 + g * 32 + tc]);
#pragma unroll
            for (int ii = 0; ii < 4; ++ii) an[ii] = hsm[tr * 4 + ii][kn];
#pragma unroll
            for (int g = 0; g < 3; ++g) {
#pragma unroll
                for (int ii = 0; ii < 4; ++ii) {
                    acc[ii][g][0] += ac[ii] * bc[g].x;
                    acc[ii][g][1] += ac[ii] * bc[g].y;
                    acc[ii][g][2] += ac[ii] * bc[g].z;
                    acc[ii][g][3] += ac[ii] * bc[g].w;
                }
            }
#pragma unroll
            for (int g = 0; g < 3; ++g) bc[g] = bn[g];
#pragma unroll
            for (int ii = 0; ii < 4; ++ii) ac[ii] = an[ii];
        }
        __syncthreads();

        if (!comb) {
#pragma unroll
            for (int ii = 0; ii < 4; ++ii) {
                const int r = tr * 4 + ii;
#pragma unroll
                for (int g = 0; g < 3; ++g)
                    *(float4*)&psum[r][g * HID + tc * 4] =
                        make_float4(acc[ii][g][0], acc[ii][g][1],
                                    acc[ii][g][2], acc[ii][g][3]);
            }
        }
        __syncthreads();

        if (comb) {
            const size_t rowbase = (size_t)step * BATCH + rb;
#pragma unroll
            for (int ii = 0; ii < 4; ++ii) {
                const int r = tr * 4 + ii;
                const float* gb = gi + (rowbase + r) * G3;
                float4 gr = __ldg((const float4*)(gb + tc * 4));
                float4 gz = __ldg((const float4*)(gb + HID + tc * 4));
                float4 gn = __ldg((const float4*)(gb + 2 * HID + tc * 4));
                float4 p0 = *(const float4*)&psum[r][0 * HID + tc * 4];
                float4 p1 = *(const float4*)&psum[r][1 * HID + tc * 4];
                float4 p2 = *(const float4*)&psum[r][2 * HID + tc * 4];
                float4 ho = *(const float4*)&hsm[r][tc * 4];
                float irv[4] = {gr.x, gr.y, gr.z, gr.w};
                float izv[4] = {gz.x, gz.y, gz.z, gz.w};
                float inv[4] = {gn.x, gn.y, gn.z, gn.w};
                float hv [4] = {ho.x, ho.y, ho.z, ho.w};
                float pr [4] = {p0.x, p0.y, p0.z, p0.w};
                float pz [4] = {p1.x, p1.y, p1.z, p1.w};
                float pn [4] = {p2.x, p2.y, p2.z, p2.w};
                float ov[4];
#pragma unroll
                for (int o = 0; o < 4; ++o) {
                    float hr = acc[ii][0][o] + pr[o] + bq[0][o];
                    float hz = acc[ii][1][o] + pz[o] + bq[1][o];
                    float hn = acc[ii][2][o] + pn[o] + bq[2][o];
                    float rg = 1.f / (1.f + __expf(-(irv[o] + hr)));
                    float zg = 1.f / (1.f + __expf(-(izv[o] + hz)));
                    float ng = tanhf(inv[o] + rg * hn);
                    ov[o] = (1.f - zg) * ng + zg * hv[o];
                }
                float4 hn4 = make_float4(ov[0], ov[1], ov[2], ov[3]);
                *(float4*)&hsm[r][tc * 4] = hn4;
                if (hall)
                    *(float4*)&hall[(rowbase + r) * HID + tc * 4] = hn4;
            }
        }
        __syncthreads();
    }

    // fused feature projection: g_feat[rb+r] = hsm[r] @ W1^T + b1
    if (W1) {
        for (int t = tid; t < 32 * FEAT; t += 512) {
            int r = t / FEAT, o = t % FEAT;
            float s = b1[o];
            const float* w = W1 + (size_t)o * HID;
#pragma unroll 8
            for (int k = 0; k < HID; ++k) s += hsm[r][k] * w[k];
            g_feat[(size_t)(rb + r) * FEAT + o] = s;
        }
    }
}

// ---------------- pairwise sq-dist: conflict-free compute, coalesced diag-major writes ----------------
__global__ void pairdist_kernel() {
    __shared__ float s1[32][31];
    __shared__ float s2[32][31];
    __shared__ float dtile[32][34];   // stride 34 -> diag reads conflict-free
    int tid = threadIdx.y * 32 + threadIdx.x;
    int i0 = blockIdx.y * 32, j0 = blockIdx.x * 32;
    for (int idx = tid; idx < 32 * FEAT; idx += 1024) {
        int r = idx / FEAT, c = idx % FEAT;
        s1[r][c] = g_feat[(size_t)(i0 + r) * FEAT + c];
        s2[r][c] = g_feat[(size_t)(NW + j0 + r) * FEAT + c];
    }
    __syncthreads();
    float d = 0.f;
#pragma unroll
    for (int c = 0; c < FEAT; c++) {
        float t = s1[threadIdx.y][c] - s2[threadIdx.x][c];
        d += t * t;
    }
    dtile[threadIdx.y][threadIdx.x] = d * LOG2E;
    __syncthreads();
    // write 63 anti-diagonals, coalesced in i
    int w = tid >> 5, l = tid & 31;
#pragma unroll
    for (int kd = w; kd < 63; kd += 32) {
        int imin = kd > 31 ? kd - 31 : 0;
        int imax = kd < 31 ? kd : 31;
        int i = imin + l;
        if (i <= imax)
            g_Dd[(size_t)(i0 + j0 + kd) * NW + (i0 + i)] = dtile[i][kd - i];
    }
}

// ---------------- soft-DTW: branch-free pipelined wavefront ----------------
__global__ void __launch_bounds__(32)
softdtw_wave(float* __restrict__ out) {
    const int s = blockIdx.x;
    const int lane = threadIdx.x;

    float v1  = INF_S;                               // R[i][j-1]
    float u1p = (lane == 0 && s == 0) ? 0.f : INF_S; // previous step's up = diag source
    float rpbuf = INF_S;
    float vlast = 0.f;

    const float* dp = g_Dd + (size_t)(s * 32) * NW + (s * 32 + lane);
    float dbuf[8];
#pragma unroll
    for (int q = 0; q < 8; ++q)
        dbuf[q] = __ldg(dp + (size_t)q * NW);

    const float* rowprev = g_row + (size_t)(s - 1) * NW;
    float* rowmine = g_row + (size_t)s * NW;
    int* myflag = &g_flag[s];
    int flagseen = 0;
    const int s0 = (s == 0);
    const int pub = (lane == 31) & (s < 63);

    for (int c = 0; c < 130; ++c) {
        const int t0 = c * 16;
        if (s > 0 && t0 < NW) {
            const int need = c + 1;
            if (flagseen < need)
                while ((flagseen = ldacq(&g_flag[s - 1])) < need) { }
            rpbuf = (lane < 16) ? rowprev[t0 + lane] : INF_S;
        }
#pragma unroll
        for (int q = 0; q < 16; ++q) {
            const int t = t0 + q;
            const int j = t - lane;
            float u1  = __shfl_up_sync(0xffffffffu, v1, 1);
            float rbc = __shfl_sync(0xffffffffu, rpbuf, q);
            u1 = (lane == 0) ? (s0 ? INF_S : rbc) : u1;
            float u2 = u1p;
            float dval = dbuf[t & 7];
            dbuf[t & 7] = __ldg(dp + (size_t)(t + 8) * NW);   // padded rows: safe
            float mn = fminf(v1, fminf(u1, u2));
            float e  = ex2f(mn - u2) + ex2f(mn - u1) + ex2f(mn - v1);
            float v  = dval + mn - lg2f(e);
            const int active = (j >= 0) & (j < NW);
            v1 = active ? v : v1;
            u1p = u1;
            vlast = (active & (j == NW - 1)) ? v : vlast;
            stg_pred(rowmine + j, v, pub & active);
            red_rel_pred(myflag, pub & active & ((j & 15) == 15));
        }
    }
    if (s == 63 && lane == 31) out[0] = vlast * LN2;
}

// ---------------- host orchestration ----------------
extern "C" void kernel_launch(void* const* d_in, const int* in_sizes, int n_in,
                              void* d_out, int out_size) {
    const float* x    = (const float*)d_in[0];
    const float* y    = (const float*)d_in[1];
    const float* Wih1 = (const float*)d_in[2];
    const float* Whh1 = (const float*)d_in[3];
    const float* bih1 = (const float*)d_in[4];
    const float* bhh1 = (const float*)d_in[5];
    const float* Wih2 = (const float*)d_in[6];
    const float* Whh2 = (const float*)d_in[7];
    const float* bih2 = (const float*)d_in[8];
    const float* bhh2 = (const float*)d_in[9];
    const float* W1   = (const float*)d_in[10];
    const float* b1   = (const float*)d_in[11];
    float* out = (float*)d_out;

    float *seq, *gi, *h1all, *whT1, *whT2;
    cudaGetSymbolAddress((void**)&seq,   g_seq);
    cudaGetSymbolAddress((void**)&gi,    g_gi);
    cudaGetSymbolAddress((void**)&h1all, g_h1all);
    cudaGetSymbolAddress((void**)&whT1,  g_WhhT1);
    cudaGetSymbolAddress((void**)&whT2,  g_WhhT2);

    const int GRU_SMEM = (32 * HID + 32 * G3) * 4;   // 64 KB
    cudaFuncSetAttribute(gru_layer_kernel,
                         cudaFuncAttributeMaxDynamicSharedMemorySize, GRU_SMEM);

    // 1) prep: windows + weight transpose + flag reset
    {
        int total = STEPS * BATCH * IN_F;
        prep_kernel<<<(total + 255) / 256, 256>>>(x, y, Whh1, Whh2);
    }

    // 2) layer-1 input gates: (8*4096,384) = seq @ Wih1^T  (K=72)
    sgemm_db<8><<<dim3(G3 / 128, (STEPS * BATCH) / 128), 256>>>(
        seq, Wih1, bih1, gi, STEPS * BATCH, G3, IN_F);

    // 3) layer-1 recurrence
    gru_layer_kernel<<<BATCH / 32, 512, GRU_SMEM>>>(
        gi, (const float4*)whT1, bhh1, h1all, nullptr, nullptr);

    // 4) layer-2 input gates: h1all @ Wih2^T  (K=128)
    sgemm_db<16><<<dim3(G3 / 128, (STEPS * BATCH) / 128), 256>>>(
        h1all, Wih2, bih2, gi, STEPS * BATCH, G3, HID);

    // 5) layer-2 recurrence + fused feature projection
    gru_layer_kernel<<<BATCH / 32, 512, GRU_SMEM>>>(
        gi, (const float4*)whT2, bhh2, nullptr, W1, b1);

    // 6) pairwise distances (diag-major, coalesced writes)
    pairdist_kernel<<<dim3(NW / 32, NW / 32), dim3(32, 32)>>>();

    // 7) soft-DTW branch-free wavefront
    softdtw_wave<<<64, 32>>>(out);
}

// round 5
// speedup vs baseline: 3.0161x; 1.0016x over previous
#include <cuda_runtime.h>
#include <math.h>

#define T_LEN   8196
#define WIN     8
#define STRIDE  4
#define NW      2048
#define BATCH   4096
#define IN_F    72
#define HID     128
#define G3      384
#define FEAT    30
#define STEPS   8
#define INF_S   1.44269504e10f   // 1e10 * log2(e): DP runs in log2e-scaled domain
#define LOG2E   1.44269504f
#define LN2     0.693147180559945f

#define NSTRIP  32               // soft-DTW strips of 64 rows
#define SS_CHUNKS 132            // 132 chunks x 8 supersteps = 1056
#define D_TPAD  1064             // superstep dim incl. prefetch pad

// ---------------- static scratch ----------------
__device__ float g_seq  [STEPS * BATCH * IN_F];
__device__ float g_gi   [STEPS * BATCH * G3];
__device__ float g_h1all[STEPS * BATCH * HID];
__device__ float g_feat [BATCH * FEAT];
__device__ float g_Ds   [NSTRIP * D_TPAD * 32 * 4];   // skewed 2x2-block D, 17.4MB
__device__ float g_WhhT1[HID * G3];
__device__ float g_WhhT2[HID * G3];
__device__ float2 g_row2[NSTRIP * 1024];              // bottom-row col-pair handoff
__device__ int   g_flag2[NSTRIP * 32];                // flags padded to 128B apart

// ---------------- PTX helpers ----------------
__device__ __forceinline__ float ex2f(float x) {
    float r; asm("ex2.approx.ftz.f32 %0, %1;" : "=f"(r) : "f"(x)); return r;
}
__device__ __forceinline__ float lg2f(float x) {
    float r; asm("lg2.approx.ftz.f32 %0, %1;" : "=f"(r) : "f"(x)); return r;
}
__device__ __forceinline__ int ldacq(const int* p) {
    int v; asm volatile("ld.acquire.gpu.global.b32 %0, [%1];" : "=r"(v) : "l"(p) : "memory"); return v;
}
__device__ __forceinline__ void stg_pred(float* p, float v, int pred) {
    asm volatile("{\n\t.reg .pred p;\n\tsetp.ne.s32 p, %0, 0;\n\t@p st.global.f32 [%1], %2;\n\t}"
                 :: "r"(pred), "l"(p), "f"(v) : "memory");
}
__device__ __forceinline__ void stg2_pred(float2* p, float v0, float v1, int pred) {
    asm volatile("{\n\t.reg .pred p;\n\tsetp.ne.s32 p, %0, 0;\n\t@p st.global.v2.f32 [%1], {%2, %3};\n\t}"
                 :: "r"(pred), "l"(p), "f"(v0), "f"(v1) : "memory");
}
__device__ __forceinline__ void red_rel_pred(int* p, int pred) {
    asm volatile("{\n\t.reg .pred p;\n\tsetp.ne.s32 p, %0, 0;\n\t@p red.release.gpu.global.add.u32 [%1], 1;\n\t}"
                 :: "r"(pred), "l"(p) : "memory");
}

// softmin cell in log2 domain: softmin(diag, up, left) + d
__device__ __forceinline__ float cellf(float d, float lf, float up, float dg) {
    float mn = fminf(lf, fminf(up, dg));
    float e  = ex2f(mn - dg) + ex2f(mn - up) + ex2f(mn - lf);
    return d + mn - lg2f(e);
}

// ---------------- prep: windows + weight transpose + flag reset ----------------
__global__ void prep_kernel(const float* __restrict__ x, const float* __restrict__ y,
                            const float* __restrict__ Whh1, const float* __restrict__ Whh2) {
    int idx = blockIdx.x * blockDim.x + threadIdx.x;
    const int total = STEPS * BATCH * IN_F;
    if (idx < total) {
        int f = idx % IN_F;
        int b = (idx / IN_F) % BATCH;
        int s = idx / (IN_F * BATCH);
        const float* src = (b < NW) ? x : y;
        int w = b & (NW - 1);
        g_seq[idx] = src[(size_t)f * T_LEN + w * STRIDE + s];
    }
    if (idx < HID * G3) {
        int k = idx / G3, n = idx % G3;
        g_WhhT1[idx] = Whh1[(size_t)n * HID + k];
        g_WhhT2[idx] = Whh2[(size_t)n * HID + k];
    }
    if (idx < NSTRIP) g_flag2[idx * 32] = 0;
}

// ---------------- SGEMM (double-buffered, warp-tiled): C = A@B^T + bias ----------------
template<int BK>
__global__ void __launch_bounds__(256)
sgemm_db(const float* __restrict__ A, const float* __restrict__ Bw,
         const float* __restrict__ bias, float* __restrict__ C,
         int M, int N, int K) {
    constexpr int BM = 128, BN = 128;
    constexpr int PAD = 4;
    constexpr int C4S = BK / 4;
    constexpr int NL  = (BM * BK / 4) / 256;

    __shared__ float As[2][BK][BM + PAD];
    __shared__ float Bs[2][BK][BN + PAD];

    const int tid = threadIdx.x;
    const int rb = blockIdx.y * BM;
    const int cb = blockIdx.x * BN;
    const int warp = tid >> 5, lane = tid & 31;
    const int wr = (warp & 3) * 32;
    const int wc = (warp >> 2) * 64;
    const int lr = ((lane >> 3) & 3) * 8;
    const int lc = (lane & 7) * 8;

    const int nt = K / BK;

    float4 aR[NL], bR[NL];
    int lrow[NL], lcc[NL];
#pragma unroll
    for (int i = 0; i < NL; ++i) {
        int idx = tid + i * 256;
        lrow[i] = idx / C4S;
        lcc[i]  = idx % C4S;
    }

    auto loadT = [&](int t) {
#pragma unroll
        for (int i = 0; i < NL; ++i) {
            aR[i] = *(const float4*)&A[(size_t)(rb + lrow[i]) * K + t * BK + lcc[i] * 4];
            bR[i] = *(const float4*)&Bw[(size_t)(cb + lrow[i]) * K + t * BK + lcc[i] * 4];
        }
    };
    auto storeT = [&](int buf) {
#pragma unroll
        for (int i = 0; i < NL; ++i) {
            As[buf][lcc[i] * 4 + 0][lrow[i]] = aR[i].x;
            As[buf][lcc[i] * 4 + 1][lrow[i]] = aR[i].y;
            As[buf][lcc[i] * 4 + 2][lrow[i]] = aR[i].z;
            As[buf][lcc[i] * 4 + 3][lrow[i]] = aR[i].w;
            Bs[buf][lcc[i] * 4 + 0][lrow[i]] = bR[i].x;
            Bs[buf][lcc[i] * 4 + 1][lrow[i]] = bR[i].y;
            Bs[buf][lcc[i] * 4 + 2][lrow[i]] = bR[i].z;
            Bs[buf][lcc[i] * 4 + 3][lrow[i]] = bR[i].w;
        }
    };

    float acc[8][8];
#pragma unroll
    for (int i = 0; i < 8; i++)
#pragma unroll
        for (int j = 0; j < 8; j++) acc[i][j] = 0.f;

    loadT(0);
    storeT(0);
    __syncthreads();

    for (int t = 0; t < nt; ++t) {
        const int cur = t & 1;
        if (t + 1 < nt) loadT(t + 1);
#pragma unroll
        for (int kk = 0; kk < BK; ++kk) {
            float4 a0 = *(const float4*)&As[cur][kk][wr + lr];
            float4 a1 = *(const float4*)&As[cur][kk][wr + lr + 4];
            float4 b0 = *(const float4*)&Bs[cur][kk][wc + lc];
            float4 b1 = *(const float4*)&Bs[cur][kk][wc + lc + 4];
            float ra[8]  = {a0.x, a0.y, a0.z, a0.w, a1.x, a1.y, a1.z, a1.w};
            float rbv[8] = {b0.x, b0.y, b0.z, b0.w, b1.x, b1.y, b1.z, b1.w};
#pragma unroll
            for (int i = 0; i < 8; i++)
#pragma unroll
                for (int j = 0; j < 8; j++)
                    acc[i][j] += ra[i] * rbv[j];
        }
        if (t + 1 < nt) storeT((t + 1) & 1);
        __syncthreads();
    }

    float bv[8];
#pragma unroll
    for (int j = 0; j < 8; j++) bv[j] = bias[cb + wc + lc + j];
#pragma unroll
    for (int i = 0; i < 8; i++) {
        int row = rb + wr + lr + i;
        float4 o0 = make_float4(acc[i][0] + bv[0], acc[i][1] + bv[1],
                                acc[i][2] + bv[2], acc[i][3] + bv[3]);
        float4 o1 = make_float4(acc[i][4] + bv[4], acc[i][5] + bv[5],
                                acc[i][6] + bv[6], acc[i][7] + bv[7]);
        *(float4*)&C[(size_t)row * N + cb + wc + lc]     = o0;
        *(float4*)&C[(size_t)row * N + cb + wc + lc + 4] = o1;
    }
}

// ---------------- persistent GRU layer (split-K, pipelined k-loop, optional feats) ----------------
__global__ void __launch_bounds__(512)
gru_layer_kernel(const float* __restrict__ gi,
                 const float4* __restrict__ W4,
                 const float* __restrict__ bhh,
                 float* __restrict__ hall,
                 const float* __restrict__ W1,
                 const float* __restrict__ b1)
{
    extern __shared__ float sraw[];
    float (*hsm)[HID] = (float (*)[HID])sraw;
    float (*psum)[G3] = (float (*)[G3])(sraw + 32 * HID);

    const int tid = threadIdx.x;
    const int kh  = tid >> 8;
    const int gt  = tid & 255;
    const int tr  = gt >> 5;
    const int tc  = gt & 31;
    const int rb  = blockIdx.x * 32;
    const int kbase = kh * 64;
    const bool comb = (kh == 0) ? (tr < 4) : (tr >= 4);

    for (int m = tid; m < 32 * HID; m += 512) sraw[m] = 0.f;
    __syncthreads();

    float bq[3][4];
#pragma unroll
    for (int g = 0; g < 3; ++g) {
        float4 bb = *(const float4*)&bhh[g * HID + tc * 4];
        bq[g][0] = bb.x; bq[g][1] = bb.y; bq[g][2] = bb.z; bq[g][3] = bb.w;
    }

    for (int step = 0; step < STEPS; ++step) {
        float acc[4][3][4];
#pragma unroll
        for (int ii = 0; ii < 4; ++ii)
#pragma unroll
            for (int g = 0; g < 3; ++g)
#pragma unroll
                for (int o = 0; o < 4; ++o) acc[ii][g][o] = 0.f;

        float4 bc[3]; float ac[4];
#pragma unroll
        for (int g = 0; g < 3; ++g) bc[g] = __ldg(&W4[kbase * 96 + g * 32 + tc]);
#pragma unroll
        for (int ii = 0; ii < 4; ++ii) ac[ii] = hsm[tr * 4 + ii][kbase];

#pragma unroll 2
        for (int kk = 0; kk < 64; ++kk) {
            const int kn = kbase + ((kk + 1) & 63);
            float4 bn[3]; float an[4];
#pragma unroll
            for (int g = 0; g < 3; ++g) bn[g] = __ldg(&W4[kn * 96 + g * 32 + tc]);
#pragma unroll
            for (int ii = 0; ii < 4; ++ii) an[ii] = hsm[tr * 4 + ii][kn];
#pragma unroll
            for (int g = 0; g < 3; ++g) {
#pragma unroll
                for (int ii = 0; ii < 4; ++ii) {
                    acc[ii][g][0] += ac[ii] * bc[g].x;
                    acc[ii][g][1] += ac[ii] * bc[g].y;
                    acc[ii][g][2] += ac[ii] * bc[g].z;
                    acc[ii][g][3] += ac[ii] * bc[g].w;
                }
            }
#pragma unroll
            for (int g = 0; g < 3; ++g) bc[g] = bn[g];
#pragma unroll
            for (int ii = 0; ii < 4; ++ii) ac[ii] = an[ii];
        }
        __syncthreads();

        if (!comb) {
#pragma unroll
            for (int ii = 0; ii < 4; ++ii) {
                const int r = tr * 4 + ii;
#pragma unroll
                for (int g = 0; g < 3; ++g)
                    *(float4*)&psum[r][g * HID + tc * 4] =
                        make_float4(acc[ii][g][0], acc[ii][g][1],
                                    acc[ii][g][2], acc[ii][g][3]);
            }
        }
        __syncthreads();

        if (comb) {
            const size_t rowbase = (size_t)step * BATCH + rb;
#pragma unroll
            for (int ii = 0; ii < 4; ++ii) {
                const int r = tr * 4 + ii;
                const float* gb = gi + (rowbase + r) * G3;
                float4 gr = __ldg((const float4*)(gb + tc * 4));
                float4 gz = __ldg((const float4*)(gb + HID + tc * 4));
                float4 gn = __ldg((const float4*)(gb + 2 * HID + tc * 4));
                float4 p0 = *(const float4*)&psum[r][0 * HID + tc * 4];
                float4 p1 = *(const float4*)&psum[r][1 * HID + tc * 4];
                float4 p2 = *(const float4*)&psum[r][2 * HID + tc * 4];
                float4 ho = *(const float4*)&hsm[r][tc * 4];
                float irv[4] = {gr.x, gr.y, gr.z, gr.w};
                float izv[4] = {gz.x, gz.y, gz.z, gz.w};
                float inv[4] = {gn.x, gn.y, gn.z, gn.w};
                float hv [4] = {ho.x, ho.y, ho.z, ho.w};
                float pr [4] = {p0.x, p0.y, p0.z, p0.w};
                float pz [4] = {p1.x, p1.y, p1.z, p1.w};
                float pn [4] = {p2.x, p2.y, p2.z, p2.w};
                float ov[4];
#pragma unroll
                for (int o = 0; o < 4; ++o) {
                    float hr = acc[ii][0][o] + pr[o] + bq[0][o];
                    float hz = acc[ii][1][o] + pz[o] + bq[1][o];
                    float hn = acc[ii][2][o] + pn[o] + bq[2][o];
                    float rg = 1.f / (1.f + __expf(-(irv[o] + hr)));
                    float zg = 1.f / (1.f + __expf(-(izv[o] + hz)));
                    float ng = tanhf(inv[o] + rg * hn);
                    ov[o] = (1.f - zg) * ng + zg * hv[o];
                }
                float4 hn4 = make_float4(ov[0], ov[1], ov[2], ov[3]);
                *(float4*)&hsm[r][tc * 4] = hn4;
                if (hall)
                    *(float4*)&hall[(rowbase + r) * HID + tc * 4] = hn4;
            }
        }
        __syncthreads();
    }

    if (W1) {
        for (int t = tid; t < 32 * FEAT; t += 512) {
            int r = t / FEAT, o = t % FEAT;
            float s = b1[o];
            const float* w = W1 + (size_t)o * HID;
#pragma unroll 8
            for (int k = 0; k < HID; ++k) s += hsm[r][k] * w[k];
            g_feat[(size_t)(rb + r) * FEAT + o] = s;
        }
    }
}

// ---------------- pairwise sq-dist -> skewed 2x2-block layout for softdtw ----------------
// g_Ds[s][t][l] float4 = (d(2l',2c), d(2l',2c+1), d(2l'+1,2c), d(2l'+1,2c+1)),
// where i = 64s + 2l' + rp, j = 2c + jp, t = c + l'.
__global__ void pairdist_kernel() {
    __shared__ float s1[32][31];
    __shared__ float s2[32][31];
    int tid = threadIdx.y * 32 + threadIdx.x;
    int i0 = blockIdx.y * 32, j0 = blockIdx.x * 32;
    for (int idx = tid; idx < 32 * FEAT; idx += 1024) {
        int r = idx / FEAT, c = idx % FEAT;
        s1[r][c] = g_feat[(size_t)(i0 + r) * FEAT + c];
        s2[r][c] = g_feat[(size_t)(NW + j0 + r) * FEAT + c];
    }
    __syncthreads();
    int i = i0 + threadIdx.y, j = j0 + threadIdx.x;
    float d = 0.f;
#pragma unroll
    for (int c = 0; c < FEAT; c++) {
        float t = s1[threadIdx.y][c] - s2[threadIdx.x][c];
        d += t * t;
    }
    int s  = i >> 6;
    int l  = (i >> 1) & 31;
    int rp = i & 1;
    int cc = j >> 1;
    int jp = j & 1;
    int t  = cc + l;
    g_Ds[(((size_t)s * D_TPAD + t) * 32 + l) * 4 + rp * 2 + jp] = d * LOG2E;
}

// ---------------- soft-DTW: 2x2 cell blocks per lane, 32-strip pipeline ----------------
// Strip s: rows [64s, 64s+64). Lane l: rows r0=64s+2l, r1=r0+1.
// Superstep t: col pair c = t - l (cols 2c, 2c+1), active iff 0 <= c < 1024.
// 4 cells per lane per superstep, chain = shfl + 3 serial softmin cells.
__global__ void __launch_bounds__(32)
softdtw_wave2(float* __restrict__ out) {
    const int s = blockIdx.x;
    const int lane = threadIdx.x;
    const int is31  = (lane == 31);
    const int isS31 = (s == NSTRIP - 1);
    const int pubp  = is31 & !isS31;

    float vA = INF_S;   // R[r0][2c-1] (own row0 left)
    float vB = INF_S;   // R[r1][2c-1] (own row1 left) == published pair .y
    float pb0 = INF_S;  // R[r1][2c-2] (published pair .x)
    float carry = (s == 0 && lane == 0) ? 0.f : INF_S;   // diag seed / nU1 carry
    float rp0 = INF_S, rp1 = INF_S;                      // rowprev chunk regs (lanes 0..7)

    const float4* dsp = ((const float4*)g_Ds) + (size_t)s * D_TPAD * 32 + lane;
    float4 dbuf[4];
#pragma unroll
    for (int q = 0; q < 4; ++q) dbuf[q] = __ldg(dsp + (size_t)q * 32);

    const float2* rowprev = g_row2 + (size_t)(s - 1) * 1024;
    float2* rowmine = g_row2 + (size_t)s * 1024;
    int* myflag = &g_flag2[s * 32];
    const int* prevflag = &g_flag2[(s - 1) * 32];
    int flagseen = 0;

    for (int C = 0; C < SS_CHUNKS; ++C) {
        if (s > 0 && C < 128) {
            const int need = C + 1;
            if (flagseen < need)
                while ((flagseen = ldacq(prevflag)) < need) { }
            if (lane < 8) {
                float2 rp = __ldg(&rowprev[C * 8 + lane]);
                rp0 = rp.x; rp1 = rp.y;
            } else {
                rp0 = INF_S; rp1 = INF_S;
            }
        }
#pragma unroll
        for (int q = 0; q < 8; ++q) {
            const int t = C * 8 + q;
            const int c = t - lane;
            // up pair from neighbor's committed (r1) values of t-1; rowprev for lane 0
            float s0 = __shfl_up_sync(0xffffffffu, pb0, 1);
            float s1 = __shfl_up_sync(0xffffffffu, vB, 1);
            float r0q = __shfl_sync(0xffffffffu, rp0, q);
            float r1q = __shfl_sync(0xffffffffu, rp1, q);
            float nU0 = (lane == 0) ? r0q : s0;
            float nU1 = (lane == 0) ? r1q : s1;
            float nD  = carry;

            float4 d = dbuf[t & 3];
            dbuf[t & 3] = __ldg(dsp + (size_t)(t + 4) * 32);

            float a0 = cellf(d.x, vA, nU0, nD);   // (r0, 2c)
            float a1 = cellf(d.y, a0, nU1, nU0);  // (r0, 2c+1)
            float b0 = cellf(d.z, vB, a0, vA);    // (r1, 2c)
            float b1 = cellf(d.w, b0, a1, a0);    // (r1, 2c+1)

            const int active = (c >= 0) & (c < 1024);
            carry = nU1;
            vA  = active ? a1 : vA;
            pb0 = active ? b0 : pb0;
            vB  = active ? b1 : vB;

            stg2_pred(rowmine + c, pb0, vB, active & pubp);
            red_rel_pred(myflag, active & pubp & ((c & 7) == 7));
            stg_pred(out, b1 * LN2, active & is31 & isS31 & (c == 1023));
        }
    }
}

// ---------------- host orchestration ----------------
extern "C" void kernel_launch(void* const* d_in, const int* in_sizes, int n_in,
                              void* d_out, int out_size) {
    const float* x    = (const float*)d_in[0];
    const float* y    = (const float*)d_in[1];
    const float* Wih1 = (const float*)d_in[2];
    const float* Whh1 = (const float*)d_in[3];
    const float* bih1 = (const float*)d_in[4];
    const float* bhh1 = (const float*)d_in[5];
    const float* Wih2 = (const float*)d_in[6];
    const float* Whh2 = (const float*)d_in[7];
    const float* bih2 = (const float*)d_in[8];
    const float* bhh2 = (const float*)d_in[9];
    const float* W1   = (const float*)d_in[10];
    const float* b1   = (const float*)d_in[11];
    float* out = (float*)d_out;

    float *seq, *gi, *h1all, *whT1, *whT2;
    cudaGetSymbolAddress((void**)&seq,   g_seq);
    cudaGetSymbolAddress((void**)&gi,    g_gi);
    cudaGetSymbolAddress((void**)&h1all, g_h1all);
    cudaGetSymbolAddress((void**)&whT1,  g_WhhT1);
    cudaGetSymbolAddress((void**)&whT2,  g_WhhT2);

    const int GRU_SMEM = (32 * HID + 32 * G3) * 4;   // 64 KB
    cudaFuncSetAttribute(gru_layer_kernel,
                         cudaFuncAttributeMaxDynamicSharedMemorySize, GRU_SMEM);

    // 1) prep
    {
        int total = STEPS * BATCH * IN_F;
        prep_kernel<<<(total + 255) / 256, 256>>>(x, y, Whh1, Whh2);
    }

    // 2) layer-1 input gates: seq @ Wih1^T  (K=72)
    sgemm_db<8><<<dim3(G3 / 128, (STEPS * BATCH) / 128), 256>>>(
        seq, Wih1, bih1, gi, STEPS * BATCH, G3, IN_F);

    // 3) layer-1 recurrence
    gru_layer_kernel<<<BATCH / 32, 512, GRU_SMEM>>>(
        gi, (const float4*)whT1, bhh1, h1all, nullptr, nullptr);

    // 4) layer-2 input gates: h1all @ Wih2^T  (K=128)
    sgemm_db<16><<<dim3(G3 / 128, (STEPS * BATCH) / 128), 256>>>(
        h1all, Wih2, bih2, gi, STEPS * BATCH, G3, HID);

    // 5) layer-2 recurrence + fused feature projection
    gru_layer_kernel<<<BATCH / 32, 512, GRU_SMEM>>>(
        gi, (const float4*)whT2, bhh2, nullptr, W1, b1);

    // 6) pairwise distances -> skewed block layout
    pairdist_kernel<<<dim3(NW / 32, NW / 32), dim3(32, 32)>>>();

    // 7) soft-DTW 2x2-block wavefront
    softdtw_wave2<<<NSTRIP, 32>>>(out);
}

// round 6
// speedup vs baseline: 3.2722x; 1.0849x over previous
#include <cuda_runtime.h>
#include <math.h>

#define T_LEN   8196
#define WIN     8
#define STRIDE  4
#define NW      2048
#define BATCH   4096
#define IN_F    72
#define HID     128
#define G3      384
#define FEAT    30
#define STEPS   8
#define LOG2E   1.44269504f
#define LN2     0.693147180559945f

#define NSTRIP  32               // soft-DTW strips of 64 rows
#define SS_CHUNKS 132            // 132 chunks x 8 supersteps = 1056
#define D_TPAD  1064             // superstep dim incl. prefetch pad

// ---------------- static scratch ----------------
__device__ float g_seq  [STEPS * BATCH * IN_F];
__device__ float g_gi   [STEPS * BATCH * G3];
__device__ float g_h1all[STEPS * BATCH * HID];
__device__ float g_feat [BATCH * FEAT];
__device__ float g_Ds   [NSTRIP * D_TPAD * 32 * 4];   // skewed 2x2-block p = 2^(-d*lg2e); pads stay 0 (=INF)
__device__ float g_WhhT1[HID * G3];
__device__ float g_WhhT2[HID * G3];
__device__ float4 g_row4[NSTRIP * 1024];              // handoff: (E_b0, E_b1, M, 0) raw
__device__ int   g_flag2[NSTRIP * 32];                // flags 128B apart

// ---------------- PTX helpers ----------------
__device__ __forceinline__ float ex2f(float x) {
    float r; asm("ex2.approx.ftz.f32 %0, %1;" : "=f"(r) : "f"(x)); return r;
}
__device__ __forceinline__ float lg2f(float x) {
    float r; asm("lg2.approx.ftz.f32 %0, %1;" : "=f"(r) : "f"(x)); return r;
}
__device__ __forceinline__ int ldacq(const int* p) {
    int v; asm volatile("ld.acquire.gpu.global.b32 %0, [%1];" : "=r"(v) : "l"(p) : "memory"); return v;
}
__device__ __forceinline__ void stg_pred(float* p, float v, int pred) {
    asm volatile("{\n\t.reg .pred p;\n\tsetp.ne.s32 p, %0, 0;\n\t@p st.global.f32 [%1], %2;\n\t}"
                 :: "r"(pred), "l"(p), "f"(v) : "memory");
}
__device__ __forceinline__ void stg4_pred(float4* p, float a, float b, float c, int pred) {
    asm volatile("{\n\t.reg .pred p;\n\tsetp.ne.s32 p, %0, 0;\n\t@p st.global.v4.f32 [%1], {%2, %3, %4, %5};\n\t}"
                 :: "r"(pred), "l"(p), "f"(a), "f"(b), "f"(c), "f"(0.f) : "memory");
}
__device__ __forceinline__ void red_rel_pred(int* p, int pred) {
    asm volatile("{\n\t.reg .pred p;\n\tsetp.ne.s32 p, %0, 0;\n\t@p red.release.gpu.global.add.u32 [%1], 1;\n\t}"
                 :: "r"(pred), "l"(p) : "memory");
}

// ---------------- prep ----------------
__global__ void prep_kernel(const float* __restrict__ x, const float* __restrict__ y,
                            const float* __restrict__ Whh1, const float* __restrict__ Whh2) {
    int idx = blockIdx.x * blockDim.x + threadIdx.x;
    const int total = STEPS * BATCH * IN_F;
    if (idx < total) {
        int f = idx % IN_F;
        int b = (idx / IN_F) % BATCH;
        int s = idx / (IN_F * BATCH);
        const float* src = (b < NW) ? x : y;
        int w = b & (NW - 1);
        g_seq[idx] = src[(size_t)f * T_LEN + w * STRIDE + s];
    }
    if (idx < HID * G3) {
        int k = idx / G3, n = idx % G3;
        g_WhhT1[idx] = Whh1[(size_t)n * HID + k];
        g_WhhT2[idx] = Whh2[(size_t)n * HID + k];
    }
    if (idx < NSTRIP) g_flag2[idx * 32] = 0;
}

// ---------------- SGEMM (double-buffered, warp-tiled): C = A@B^T + bias ----------------
template<int BK>
__global__ void __launch_bounds__(256)
sgemm_db(const float* __restrict__ A, const float* __restrict__ Bw,
         const float* __restrict__ bias, float* __restrict__ C,
         int M, int N, int K) {
    constexpr int BM = 128, BN = 128;
    constexpr int PAD = 4;
    constexpr int C4S = BK / 4;
    constexpr int NL  = (BM * BK / 4) / 256;

    __shared__ float As[2][BK][BM + PAD];
    __shared__ float Bs[2][BK][BN + PAD];

    const int tid = threadIdx.x;
    const int rb = blockIdx.y * BM;
    const int cb = blockIdx.x * BN;
    const int warp = tid >> 5, lane = tid & 31;
    const int wr = (warp & 3) * 32;
    const int wc = (warp >> 2) * 64;
    const int lr = ((lane >> 3) & 3) * 8;
    const int lc = (lane & 7) * 8;

    const int nt = K / BK;

    float4 aR[NL], bR[NL];
    int lrow[NL], lcc[NL];
#pragma unroll
    for (int i = 0; i < NL; ++i) {
        int idx = tid + i * 256;
        lrow[i] = idx / C4S;
        lcc[i]  = idx % C4S;
    }

    auto loadT = [&](int t) {
#pragma unroll
        for (int i = 0; i < NL; ++i) {
            aR[i] = *(const float4*)&A[(size_t)(rb + lrow[i]) * K + t * BK + lcc[i] * 4];
            bR[i] = *(const float4*)&Bw[(size_t)(cb + lrow[i]) * K + t * BK + lcc[i] * 4];
        }
    };
    auto storeT = [&](int buf) {
#pragma unroll
        for (int i = 0; i < NL; ++i) {
            As[buf][lcc[i] * 4 + 0][lrow[i]] = aR[i].x;
            As[buf][lcc[i] * 4 + 1][lrow[i]] = aR[i].y;
            As[buf][lcc[i] * 4 + 2][lrow[i]] = aR[i].z;
            As[buf][lcc[i] * 4 + 3][lrow[i]] = aR[i].w;
            Bs[buf][lcc[i] * 4 + 0][lrow[i]] = bR[i].x;
            Bs[buf][lcc[i] * 4 + 1][lrow[i]] = bR[i].y;
            Bs[buf][lcc[i] * 4 + 2][lrow[i]] = bR[i].z;
            Bs[buf][lcc[i] * 4 + 3][lrow[i]] = bR[i].w;
        }
    };

    float acc[8][8];
#pragma unroll
    for (int i = 0; i < 8; i++)
#pragma unroll
        for (int j = 0; j < 8; j++) acc[i][j] = 0.f;

    loadT(0);
    storeT(0);
    __syncthreads();

    for (int t = 0; t < nt; ++t) {
        const int cur = t & 1;
        if (t + 1 < nt) loadT(t + 1);
#pragma unroll
        for (int kk = 0; kk < BK; ++kk) {
            float4 a0 = *(const float4*)&As[cur][kk][wr + lr];
            float4 a1 = *(const float4*)&As[cur][kk][wr + lr + 4];
            float4 b0 = *(const float4*)&Bs[cur][kk][wc + lc];
            float4 b1 = *(const float4*)&Bs[cur][kk][wc + lc + 4];
            float ra[8]  = {a0.x, a0.y, a0.z, a0.w, a1.x, a1.y, a1.z, a1.w};
            float rbv[8] = {b0.x, b0.y, b0.z, b0.w, b1.x, b1.y, b1.z, b1.w};
#pragma unroll
            for (int i = 0; i < 8; i++)
#pragma unroll
                for (int j = 0; j < 8; j++)
                    acc[i][j] += ra[i] * rbv[j];
        }
        if (t + 1 < nt) storeT((t + 1) & 1);
        __syncthreads();
    }

    float bv[8];
#pragma unroll
    for (int j = 0; j < 8; j++) bv[j] = bias[cb + wc + lc + j];
#pragma unroll
    for (int i = 0; i < 8; i++) {
        int row = rb + wr + lr + i;
        float4 o0 = make_float4(acc[i][0] + bv[0], acc[i][1] + bv[1],
                                acc[i][2] + bv[2], acc[i][3] + bv[3]);
        float4 o1 = make_float4(acc[i][4] + bv[4], acc[i][5] + bv[5],
                                acc[i][6] + bv[6], acc[i][7] + bv[7]);
        *(float4*)&C[(size_t)row * N + cb + wc + lc]     = o0;
        *(float4*)&C[(size_t)row * N + cb + wc + lc + 4] = o1;
    }
}

// ---------------- persistent GRU layer (split-K, pipelined k-loop, optional feats) ----------------
__global__ void __launch_bounds__(512)
gru_layer_kernel(const float* __restrict__ gi,
                 const float4* __restrict__ W4,
                 const float* __restrict__ bhh,
                 float* __restrict__ hall,
                 const float* __restrict__ W1,
                 const float* __restrict__ b1)
{
    extern __shared__ float sraw[];
    float (*hsm)[HID] = (float (*)[HID])sraw;
    float (*psum)[G3] = (float (*)[G3])(sraw + 32 * HID);

    const int tid = threadIdx.x;
    const int kh  = tid >> 8;
    const int gt  = tid & 255;
    const int tr  = gt >> 5;
    const int tc  = gt & 31;
    const int rb  = blockIdx.x * 32;
    const int kbase = kh * 64;
    const bool comb = (kh == 0) ? (tr < 4) : (tr >= 4);

    for (int m = tid; m < 32 * HID; m += 512) sraw[m] = 0.f;
    __syncthreads();

    float bq[3][4];
#pragma unroll
    for (int g = 0; g < 3; ++g) {
        float4 bb = *(const float4*)&bhh[g * HID + tc * 4];
        bq[g][0] = bb.x; bq[g][1] = bb.y; bq[g][2] = bb.z; bq[g][3] = bb.w;
    }

    for (int step = 0; step < STEPS; ++step) {
        float acc[4][3][4];
#pragma unroll
        for (int ii = 0; ii < 4; ++ii)
#pragma unroll
            for (int g = 0; g < 3; ++g)
#pragma unroll
                for (int o = 0; o < 4; ++o) acc[ii][g][o] = 0.f;

        float4 bc[3]; float ac[4];
#pragma unroll
        for (int g = 0; g < 3; ++g) bc[g] = __ldg(&W4[kbase * 96 + g * 32 + tc]);
#pragma unroll
        for (int ii = 0; ii < 4; ++ii) ac[ii] = hsm[tr * 4 + ii][kbase];

#pragma unroll 2
        for (int kk = 0; kk < 64; ++kk) {
            const int kn = kbase + ((kk + 1) & 63);
            float4 bn[3]; float an[4];
#pragma unroll
            for (int g = 0; g < 3; ++g) bn[g] = __ldg(&W4[kn * 96 + g * 32 + tc]);
#pragma unroll
            for (int ii = 0; ii < 4; ++ii) an[ii] = hsm[tr * 4 + ii][kn];
#pragma unroll
            for (int g = 0; g < 3; ++g) {
#pragma unroll
                for (int ii = 0; ii < 4; ++ii) {
                    acc[ii][g][0] += ac[ii] * bc[g].x;
                    acc[ii][g][1] += ac[ii] * bc[g].y;
                    acc[ii][g][2] += ac[ii] * bc[g].z;
                    acc[ii][g][3] += ac[ii] * bc[g].w;
                }
            }
#pragma unroll
            for (int g = 0; g < 3; ++g) bc[g] = bn[g];
#pragma unroll
            for (int ii = 0; ii < 4; ++ii) ac[ii] = an[ii];
        }
        __syncthreads();

        if (!comb) {
#pragma unroll
            for (int ii = 0; ii < 4; ++ii) {
                const int r = tr * 4 + ii;
#pragma unroll
                for (int g = 0; g < 3; ++g)
                    *(float4*)&psum[r][g * HID + tc * 4] =
                        make_float4(acc[ii][g][0], acc[ii][g][1],
                                    acc[ii][g][2], acc[ii][g][3]);
            }
        }
        __syncthreads();

        if (comb) {
            const size_t rowbase = (size_t)step * BATCH + rb;
#pragma unroll
            for (int ii = 0; ii < 4; ++ii) {
                const int r = tr * 4 + ii;
                const float* gb = gi + (rowbase + r) * G3;
                float4 gr = __ldg((const float4*)(gb + tc * 4));
                float4 gz = __ldg((const float4*)(gb + HID + tc * 4));
                float4 gn = __ldg((const float4*)(gb + 2 * HID + tc * 4));
                float4 p0 = *(const float4*)&psum[r][0 * HID + tc * 4];
                float4 p1 = *(const float4*)&psum[r][1 * HID + tc * 4];
                float4 p2 = *(const float4*)&psum[r][2 * HID + tc * 4];
                float4 ho = *(const float4*)&hsm[r][tc * 4];
                float irv[4] = {gr.x, gr.y, gr.z, gr.w};
                float izv[4] = {gz.x, gz.y, gz.z, gz.w};
                float inv[4] = {gn.x, gn.y, gn.z, gn.w};
                float hv [4] = {ho.x, ho.y, ho.z, ho.w};
                float pr [4] = {p0.x, p0.y, p0.z, p0.w};
                float pz [4] = {p1.x, p1.y, p1.z, p1.w};
                float pn [4] = {p2.x, p2.y, p2.z, p2.w};
                float ov[4];
#pragma unroll
                for (int o = 0; o < 4; ++o) {
                    float hr = acc[ii][0][o] + pr[o] + bq[0][o];
                    float hz = acc[ii][1][o] + pz[o] + bq[1][o];
                    float hn = acc[ii][2][o] + pn[o] + bq[2][o];
                    float rg = 1.f / (1.f + __expf(-(irv[o] + hr)));
                    float zg = 1.f / (1.f + __expf(-(izv[o] + hz)));
                    float ng = tanhf(inv[o] + rg * hn);
                    ov[o] = (1.f - zg) * ng + zg * hv[o];
                }
                float4 hn4 = make_float4(ov[0], ov[1], ov[2], ov[3]);
                *(float4*)&hsm[r][tc * 4] = hn4;
                if (hall)
                    *(float4*)&hall[(rowbase + r) * HID + tc * 4] = hn4;
            }
        }
        __syncthreads();
    }

    if (W1) {
        for (int t = tid; t < 32 * FEAT; t += 512) {
            int r = t / FEAT, o = t % FEAT;
            float s = b1[o];
            const float* w = W1 + (size_t)o * HID;
#pragma unroll 8
            for (int k = 0; k < HID; ++k) s += hsm[r][k] * w[k];
            g_feat[(size_t)(rb + r) * FEAT + o] = s;
        }
    }
}

// ---------------- pairwise: store p = 2^(-d*log2e) in skewed 2x2-block layout ----------------
__global__ void pairdist_kernel() {
    __shared__ float s1[32][31];
    __shared__ float s2[32][31];
    int tid = threadIdx.y * 32 + threadIdx.x;
    int i0 = blockIdx.y * 32, j0 = blockIdx.x * 32;
    for (int idx = tid; idx < 32 * FEAT; idx += 1024) {
        int r = idx / FEAT, c = idx % FEAT;
        s1[r][c] = g_feat[(size_t)(i0 + r) * FEAT + c];
        s2[r][c] = g_feat[(size_t)(NW + j0 + r) * FEAT + c];
    }
    __syncthreads();
    int i = i0 + threadIdx.y, j = j0 + threadIdx.x;
    float d = 0.f;
#pragma unroll
    for (int c = 0; c < FEAT; c++) {
        float t = s1[threadIdx.y][c] - s2[threadIdx.x][c];
        d += t * t;
    }
    float p = ex2f(fmaxf(-d * LOG2E, -100.f));   // clamp so p never flushes to 0
    int s  = i >> 6;
    int l  = (i >> 1) & 31;
    int rp = i & 1;
    int cc = j >> 1;
    int jp = j & 1;
    int t  = cc + l;
    g_Ds[(((size_t)s * D_TPAD + t) * 32 + l) * 4 + rp * 2 + jp] = p;
}

// ---------------- soft-DTW: probability-domain DP, zero MUFU on the chain ----------------
// Value representation: v = M - lg2(E), per-lane exponent accumulator M (int).
// Cell: E' = p * (E_dg + E_up + E_lf), p = 2^(-d*lg2e) precomputed.
// Cross-lane/strip transfers send RAW (pre-renorm) E pairs + M; consumer rescales
// by 2^(M_self - M_nbr). Renorm (exponent re-centering) is off the critical chain.
__global__ void __launch_bounds__(32)
softdtw_prob(float* __restrict__ out) {
    const int s = blockIdx.x;
    const int lane = threadIdx.x;
    const int is31 = (lane == 31);
    const int isLast = (s == NSTRIP - 1);
    const int pubp = is31 & !isLast;

    float EA = 0.f, EB = 0.f, carry = 0.f;    // E of R[r0][2c-1], R[r1][2c-1], R[r0-1][2c-1]
    float sh0 = 0.f, sh1 = 0.f;               // raw b0,b1 of last committed superstep (for shfl)
    int   M = 0, shM = 0;
    if (s == 0 && lane == 0) carry = 1.f;     // seed: R[-1][-1] = 0 -> E = 2^(0-0)

    const float4* dsp = ((const float4*)g_Ds) + (size_t)s * D_TPAD * 32 + lane;
    float4 dbuf[4];
#pragma unroll
    for (int q = 0; q < 4; ++q) dbuf[q] = __ldg(dsp + (size_t)q * 32);

    const float4* rowprev = g_row4 + (size_t)(s - 1) * 1024;
    float4* rowmine = g_row4 + (size_t)s * 1024;
    int* myflag = &g_flag2[s * 32];
    const int* prevflag = &g_flag2[(s - 1) * 32];
    int flagseen = 0;

    float4 rp[8];
#pragma unroll
    for (int q = 0; q < 8; ++q) rp[q] = make_float4(0.f, 0.f, 0.f, 0.f);

    for (int C = 0; C < SS_CHUNKS; ++C) {
        if (s > 0 && C < 128) {
            const int need = C + 1;
            if (flagseen < need)
                while ((flagseen = ldacq(prevflag)) < need) { }
#pragma unroll
            for (int q = 0; q < 8; ++q) rp[q] = __ldg(&rowprev[C * 8 + q]);  // warp-uniform
            if (C == 0 && lane == 0) M = (int)rp[0].z;   // align exponent with publisher
        }
#pragma unroll
        for (int q = 0; q < 8; ++q) {
            const int t = C * 8 + q;
            const int c = t - lane;
            // neighbor raw state (pre-renorm) + its M
            float nE0 = __shfl_up_sync(0xffffffffu, sh0, 1);
            float nE1 = __shfl_up_sync(0xffffffffu, sh1, 1);
            int   nM  = __shfl_up_sync(0xffffffffu, shM, 1);
            if (lane == 0) { nE0 = rp[q].x; nE1 = rp[q].y; nM = (int)rp[q].z; }
            if (c < 0) M = nM;                            // adopt scale until active
            int dmm = M - nM;
            dmm = dmm < -126 ? -126 : (dmm > 126 ? 126 : dmm);
            float sc = __uint_as_float((unsigned)(dmm + 127) << 23);
            float FB0 = nE0 * sc;                         // E(R[r0-1][2c])
            float FB1 = nE1 * sc;                         // E(R[r0-1][2c+1])

            float4 p = dbuf[t & 3];
            dbuf[t & 3] = __ldg(dsp + (size_t)(t + 4) * 32);

            float a0 = p.x * ((carry + FB0) + EA);
            float a1 = p.y * ((FB0 + FB1) + a0);
            float b0 = p.z * ((EB + EA) + a0);
            float b1 = p.w * ((b0 + a1) + a0);

            const int active = (c >= 0) & (c < 1024);

            stg4_pred(rowmine + c, b0, b1, (float)M, active & pubp);
            red_rel_pred(myflag, active & pubp & ((c & 7) == 7));
            if (isLast)
                stg_pred(out, ((float)M - lg2f(b1)) * LN2,
                         is31 & active & (c == 1023));

            // commit raw shfl copies
            sh0 = active ? b0 : sh0;
            sh1 = active ? b1 : sh1;
            shM = active ? M  : shM;
            // renorm retained state (keyed on b1's exponent), off the cross-lane chain
            int e = (__float_as_int(b1) >> 23) & 255;
            int doR = active & (e > 0) & (e < 254);
            int dm = doR ? (e - 127) : 0;
            float scR = __uint_as_float((unsigned)(254 - (doR ? e : 127)) << 23); // 2^(-dm)
            EA = (active ? a1 : EA) * scR;
            EB = (active ? b1 : EB) * scR;
            carry = FB1 * scR;
            M = M - dm;
        }
    }
}

// ---------------- host orchestration ----------------
extern "C" void kernel_launch(void* const* d_in, const int* in_sizes, int n_in,
                              void* d_out, int out_size) {
    const float* x    = (const float*)d_in[0];
    const float* y    = (const float*)d_in[1];
    const float* Wih1 = (const float*)d_in[2];
    const float* Whh1 = (const float*)d_in[3];
    const float* bih1 = (const float*)d_in[4];
    const float* bhh1 = (const float*)d_in[5];
    const float* Wih2 = (const float*)d_in[6];
    const float* Whh2 = (const float*)d_in[7];
    const float* bih2 = (const float*)d_in[8];
    const float* bhh2 = (const float*)d_in[9];
    const float* W1   = (const float*)d_in[10];
    const float* b1   = (const float*)d_in[11];
    float* out = (float*)d_out;

    float *seq, *gi, *h1all, *whT1, *whT2;
    cudaGetSymbolAddress((void**)&seq,   g_seq);
    cudaGetSymbolAddress((void**)&gi,    g_gi);
    cudaGetSymbolAddress((void**)&h1all, g_h1all);
    cudaGetSymbolAddress((void**)&whT1,  g_WhhT1);
    cudaGetSymbolAddress((void**)&whT2,  g_WhhT2);

    const int GRU_SMEM = (32 * HID + 32 * G3) * 4;   // 64 KB
    cudaFuncSetAttribute(gru_layer_kernel,
                         cudaFuncAttributeMaxDynamicSharedMemorySize, GRU_SMEM);

    // 1) prep
    {
        int total = STEPS * BATCH * IN_F;
        prep_kernel<<<(total + 255) / 256, 256>>>(x, y, Whh1, Whh2);
    }

    // 2) layer-1 input gates: seq @ Wih1^T  (K=72)
    sgemm_db<8><<<dim3(G3 / 128, (STEPS * BATCH) / 128), 256>>>(
        seq, Wih1, bih1, gi, STEPS * BATCH, G3, IN_F);

    // 3) layer-1 recurrence
    gru_layer_kernel<<<BATCH / 32, 512, GRU_SMEM>>>(
        gi, (const float4*)whT1, bhh1, h1all, nullptr, nullptr);

    // 4) layer-2 input gates: h1all @ Wih2^T  (K=128)
    sgemm_db<16><<<dim3(G3 / 128, (STEPS * BATCH) / 128), 256>>>(
        h1all, Wih2, bih2, gi, STEPS * BATCH, G3, HID);

    // 5) layer-2 recurrence + fused feature projection
    gru_layer_kernel<<<BATCH / 32, 512, GRU_SMEM>>>(
        gi, (const float4*)whT2, bhh2, nullptr, W1, b1);

    // 6) pairwise distances -> probability domain, skewed block layout
    pairdist_kernel<<<dim3(NW / 32, NW / 32), dim3(32, 32)>>>();

    // 7) soft-DTW probability-domain wavefront
    softdtw_prob<<<NSTRIP, 32>>>(out);
}

// round 7
// speedup vs baseline: 3.3133x; 1.0126x over previous
#include <cuda_runtime.h>
#include <math.h>

#define T_LEN   8196
#define WIN     8
#define STRIDE  4
#define NW      2048
#define BATCH   4096
#define IN_F    72
#define HID     128
#define G3      384
#define FEAT    30
#define STEPS   8
#define LOG2E   1.44269504f
#define LN2     0.693147180559945f

#define NSTRIP  32               // soft-DTW strips of 64 rows
#define SS_CHUNKS 132            // 132 chunks x 8 supersteps = 1056
#define D_TPAD  1064             // superstep dim incl. prefetch pad

// ---------------- static scratch ----------------
__device__ float g_seq  [STEPS * BATCH * IN_F];
__device__ float g_gi   [STEPS * BATCH * G3];
__device__ float g_h1all[STEPS * BATCH * HID];
__device__ float g_feat [BATCH * FEAT];
__device__ float g_Ds   [NSTRIP * D_TPAD * 32 * 4];   // skewed 2x2-block p = 2^(-d*lg2e)
__device__ float g_WhhT1[HID * G3];
__device__ float g_WhhT2[HID * G3];
__device__ float4 g_row4[NSTRIP * 1024];              // handoff: (E_b0, E_b1, M, 0) raw
__device__ int   g_flag2[NSTRIP * 32];                // flags 128B apart

// ---------------- PTX helpers ----------------
__device__ __forceinline__ float ex2f(float x) {
    float r; asm("ex2.approx.ftz.f32 %0, %1;" : "=f"(r) : "f"(x)); return r;
}
__device__ __forceinline__ float lg2f(float x) {
    float r; asm("lg2.approx.ftz.f32 %0, %1;" : "=f"(r) : "f"(x)); return r;
}
__device__ __forceinline__ int ldacq(const int* p) {
    int v; asm volatile("ld.acquire.gpu.global.b32 %0, [%1];" : "=r"(v) : "l"(p) : "memory"); return v;
}
__device__ __forceinline__ void stg_pred(float* p, float v, int pred) {
    asm volatile("{\n\t.reg .pred p;\n\tsetp.ne.s32 p, %0, 0;\n\t@p st.global.f32 [%1], %2;\n\t}"
                 :: "r"(pred), "l"(p), "f"(v) : "memory");
}
__device__ __forceinline__ void stg4_pred(float4* p, float a, float b, float c, int pred) {
    asm volatile("{\n\t.reg .pred p;\n\tsetp.ne.s32 p, %0, 0;\n\t@p st.global.v4.f32 [%1], {%2, %3, %4, %5};\n\t}"
                 :: "r"(pred), "l"(p), "f"(a), "f"(b), "f"(c), "f"(0.f) : "memory");
}
__device__ __forceinline__ void red_rel_pred(int* p, int pred) {
    asm volatile("{\n\t.reg .pred p;\n\tsetp.ne.s32 p, %0, 0;\n\t@p red.release.gpu.global.add.u32 [%1], 1;\n\t}"
                 :: "r"(pred), "l"(p) : "memory");
}

// ---------------- prep ----------------
__global__ void prep_kernel(const float* __restrict__ x, const float* __restrict__ y,
                            const float* __restrict__ Whh1, const float* __restrict__ Whh2) {
    int idx = blockIdx.x * blockDim.x + threadIdx.x;
    const int total = STEPS * BATCH * IN_F;
    if (idx < total) {
        int f = idx % IN_F;
        int b = (idx / IN_F) % BATCH;
        int s = idx / (IN_F * BATCH);
        const float* src = (b < NW) ? x : y;
        int w = b & (NW - 1);
        g_seq[idx] = src[(size_t)f * T_LEN + w * STRIDE + s];
    }
    if (idx < HID * G3) {
        int k = idx / G3, n = idx % G3;
        g_WhhT1[idx] = Whh1[(size_t)n * HID + k];
        g_WhhT2[idx] = Whh2[(size_t)n * HID + k];
    }
    if (idx < NSTRIP) g_flag2[idx * 32] = 0;
}

// ---------------- SGEMM (double-buffered, warp-tiled): C = A@B^T + bias ----------------
template<int BK>
__global__ void __launch_bounds__(256)
sgemm_db(const float* __restrict__ A, const float* __restrict__ Bw,
         const float* __restrict__ bias, float* __restrict__ C,
         int M, int N, int K) {
    constexpr int BM = 128, BN = 128;
    constexpr int PAD = 4;
    constexpr int C4S = BK / 4;
    constexpr int NL  = (BM * BK / 4) / 256;

    __shared__ float As[2][BK][BM + PAD];
    __shared__ float Bs[2][BK][BN + PAD];

    const int tid = threadIdx.x;
    const int rb = blockIdx.y * BM;
    const int cb = blockIdx.x * BN;
    const int warp = tid >> 5, lane = tid & 31;
    const int wr = (warp & 3) * 32;
    const int wc = (warp >> 2) * 64;
    const int lr = ((lane >> 3) & 3) * 8;
    const int lc = (lane & 7) * 8;

    const int nt = K / BK;

    float4 aR[NL], bR[NL];
    int lrow[NL], lcc[NL];
#pragma unroll
    for (int i = 0; i < NL; ++i) {
        int idx = tid + i * 256;
        lrow[i] = idx / C4S;
        lcc[i]  = idx % C4S;
    }

    auto loadT = [&](int t) {
#pragma unroll
        for (int i = 0; i < NL; ++i) {
            aR[i] = *(const float4*)&A[(size_t)(rb + lrow[i]) * K + t * BK + lcc[i] * 4];
            bR[i] = *(const float4*)&Bw[(size_t)(cb + lrow[i]) * K + t * BK + lcc[i] * 4];
        }
    };
    auto storeT = [&](int buf) {
#pragma unroll
        for (int i = 0; i < NL; ++i) {
            As[buf][lcc[i] * 4 + 0][lrow[i]] = aR[i].x;
            As[buf][lcc[i] * 4 + 1][lrow[i]] = aR[i].y;
            As[buf][lcc[i] * 4 + 2][lrow[i]] = aR[i].z;
            As[buf][lcc[i] * 4 + 3][lrow[i]] = aR[i].w;
            Bs[buf][lcc[i] * 4 + 0][lrow[i]] = bR[i].x;
            Bs[buf][lcc[i] * 4 + 1][lrow[i]] = bR[i].y;
            Bs[buf][lcc[i] * 4 + 2][lrow[i]] = bR[i].z;
            Bs[buf][lcc[i] * 4 + 3][lrow[i]] = bR[i].w;
        }
    };

    float acc[8][8];
#pragma unroll
    for (int i = 0; i < 8; i++)
#pragma unroll
        for (int j = 0; j < 8; j++) acc[i][j] = 0.f;

    loadT(0);
    storeT(0);
    __syncthreads();

    for (int t = 0; t < nt; ++t) {
        const int cur = t & 1;
        if (t + 1 < nt) loadT(t + 1);
#pragma unroll
        for (int kk = 0; kk < BK; ++kk) {
            float4 a0 = *(const float4*)&As[cur][kk][wr + lr];
            float4 a1 = *(const float4*)&As[cur][kk][wr + lr + 4];
            float4 b0 = *(const float4*)&Bs[cur][kk][wc + lc];
            float4 b1 = *(const float4*)&Bs[cur][kk][wc + lc + 4];
            float ra[8]  = {a0.x, a0.y, a0.z, a0.w, a1.x, a1.y, a1.z, a1.w};
            float rbv[8] = {b0.x, b0.y, b0.z, b0.w, b1.x, b1.y, b1.z, b1.w};
#pragma unroll
            for (int i = 0; i < 8; i++)
#pragma unroll
                for (int j = 0; j < 8; j++)
                    acc[i][j] += ra[i] * rbv[j];
        }
        if (t + 1 < nt) storeT((t + 1) & 1);
        __syncthreads();
    }

    float bv[8];
#pragma unroll
    for (int j = 0; j < 8; j++) bv[j] = bias[cb + wc + lc + j];
#pragma unroll
    for (int i = 0; i < 8; i++) {
        int row = rb + wr + lr + i;
        float4 o0 = make_float4(acc[i][0] + bv[0], acc[i][1] + bv[1],
                                acc[i][2] + bv[2], acc[i][3] + bv[3]);
        float4 o1 = make_float4(acc[i][4] + bv[4], acc[i][5] + bv[5],
                                acc[i][6] + bv[6], acc[i][7] + bv[7]);
        *(float4*)&C[(size_t)row * N + cb + wc + lc]     = o0;
        *(float4*)&C[(size_t)row * N + cb + wc + lc + 4] = o1;
    }
}

// ---------------- persistent GRU layer (split-K, pipelined k-loop, optional feats) ----------------
__global__ void __launch_bounds__(512)
gru_layer_kernel(const float* __restrict__ gi,
                 const float4* __restrict__ W4,
                 const float* __restrict__ bhh,
                 float* __restrict__ hall,
                 const float* __restrict__ W1,
                 const float* __restrict__ b1)
{
    extern __shared__ float sraw[];
    float (*hsm)[HID] = (float (*)[HID])sraw;
    float (*psum)[G3] = (float (*)[G3])(sraw + 32 * HID);

    const int tid = threadIdx.x;
    const int kh  = tid >> 8;
    const int gt  = tid & 255;
    const int tr  = gt >> 5;
    const int tc  = gt & 31;
    const int rb  = blockIdx.x * 32;
    const int kbase = kh * 64;
    const bool comb = (kh == 0) ? (tr < 4) : (tr >= 4);

    for (int m = tid; m < 32 * HID; m += 512) sraw[m] = 0.f;
    __syncthreads();

    float bq[3][4];
#pragma unroll
    for (int g = 0; g < 3; ++g) {
        float4 bb = *(const float4*)&bhh[g * HID + tc * 4];
        bq[g][0] = bb.x; bq[g][1] = bb.y; bq[g][2] = bb.z; bq[g][3] = bb.w;
    }

    for (int step = 0; step < STEPS; ++step) {
        float acc[4][3][4];
#pragma unroll
        for (int ii = 0; ii < 4; ++ii)
#pragma unroll
            for (int g = 0; g < 3; ++g)
#pragma unroll
                for (int o = 0; o < 4; ++o) acc[ii][g][o] = 0.f;

        float4 bc[3]; float ac[4];
#pragma unroll
        for (int g = 0; g < 3; ++g) bc[g] = __ldg(&W4[kbase * 96 + g * 32 + tc]);
#pragma unroll
        for (int ii = 0; ii < 4; ++ii) ac[ii] = hsm[tr * 4 + ii][kbase];

#pragma unroll 2
        for (int kk = 0; kk < 64; ++kk) {
            const int kn = kbase + ((kk + 1) & 63);
            float4 bn[3]; float an[4];
#pragma unroll
            for (int g = 0; g < 3; ++g) bn[g] = __ldg(&W4[kn * 96 + g * 32 + tc]);
#pragma unroll
            for (int ii = 0; ii < 4; ++ii) an[ii] = hsm[tr * 4 + ii][kn];
#pragma unroll
            for (int g = 0; g < 3; ++g) {
#pragma unroll
                for (int ii = 0; ii < 4; ++ii) {
                    acc[ii][g][0] += ac[ii] * bc[g].x;
                    acc[ii][g][1] += ac[ii] * bc[g].y;
                    acc[ii][g][2] += ac[ii] * bc[g].z;
                    acc[ii][g][3] += ac[ii] * bc[g].w;
                }
            }
#pragma unroll
            for (int g = 0; g < 3; ++g) bc[g] = bn[g];
#pragma unroll
            for (int ii = 0; ii < 4; ++ii) ac[ii] = an[ii];
        }
        __syncthreads();

        if (!comb) {
#pragma unroll
            for (int ii = 0; ii < 4; ++ii) {
                const int r = tr * 4 + ii;
#pragma unroll
                for (int g = 0; g < 3; ++g)
                    *(float4*)&psum[r][g * HID + tc * 4] =
                        make_float4(acc[ii][g][0], acc[ii][g][1],
                                    acc[ii][g][2], acc[ii][g][3]);
            }
        }
        __syncthreads();

        if (comb) {
            const size_t rowbase = (size_t)step * BATCH + rb;
#pragma unroll
            for (int ii = 0; ii < 4; ++ii) {
                const int r = tr * 4 + ii;
                const float* gb = gi + (rowbase + r) * G3;
                float4 gr = __ldg((const float4*)(gb + tc * 4));
                float4 gz = __ldg((const float4*)(gb + HID + tc * 4));
                float4 gn = __ldg((const float4*)(gb + 2 * HID + tc * 4));
                float4 p0 = *(const float4*)&psum[r][0 * HID + tc * 4];
                float4 p1 = *(const float4*)&psum[r][1 * HID + tc * 4];
                float4 p2 = *(const float4*)&psum[r][2 * HID + tc * 4];
                float4 ho = *(const float4*)&hsm[r][tc * 4];
                float irv[4] = {gr.x, gr.y, gr.z, gr.w};
                float izv[4] = {gz.x, gz.y, gz.z, gz.w};
                float inv[4] = {gn.x, gn.y, gn.z, gn.w};
                float hv [4] = {ho.x, ho.y, ho.z, ho.w};
                float pr [4] = {p0.x, p0.y, p0.z, p0.w};
                float pz [4] = {p1.x, p1.y, p1.z, p1.w};
                float pn [4] = {p2.x, p2.y, p2.z, p2.w};
                float ov[4];
#pragma unroll
                for (int o = 0; o < 4; ++o) {
                    float hr = acc[ii][0][o] + pr[o] + bq[0][o];
                    float hz = acc[ii][1][o] + pz[o] + bq[1][o];
                    float hn = acc[ii][2][o] + pn[o] + bq[2][o];
                    float rg = 1.f / (1.f + __expf(-(irv[o] + hr)));
                    float zg = 1.f / (1.f + __expf(-(izv[o] + hz)));
                    float ng = tanhf(inv[o] + rg * hn);
                    ov[o] = (1.f - zg) * ng + zg * hv[o];
                }
                float4 hn4 = make_float4(ov[0], ov[1], ov[2], ov[3]);
                *(float4*)&hsm[r][tc * 4] = hn4;
                if (hall)
                    *(float4*)&hall[(rowbase + r) * HID + tc * 4] = hn4;
            }
        }
        __syncthreads();
    }

    if (W1) {
        for (int t = tid; t < 32 * FEAT; t += 512) {
            int r = t / FEAT, o = t % FEAT;
            float s = b1[o];
            const float* w = W1 + (size_t)o * HID;
#pragma unroll 8
            for (int k = 0; k < HID; ++k) s += hsm[r][k] * w[k];
            g_feat[(size_t)(rb + r) * FEAT + o] = s;
        }
    }
}

// ---------------- pairwise: store p = 2^(-d*log2e) in skewed 2x2-block layout ----------------
__global__ void pairdist_kernel() {
    __shared__ float s1[32][31];
    __shared__ float s2[32][31];
    int tid = threadIdx.y * 32 + threadIdx.x;
    int i0 = blockIdx.y * 32, j0 = blockIdx.x * 32;
    for (int idx = tid; idx < 32 * FEAT; idx += 1024) {
        int r = idx / FEAT, c = idx % FEAT;
        s1[r][c] = g_feat[(size_t)(i0 + r) * FEAT + c];
        s2[r][c] = g_feat[(size_t)(NW + j0 + r) * FEAT + c];
    }
    __syncthreads();
    int i = i0 + threadIdx.y, j = j0 + threadIdx.x;
    float d = 0.f;
#pragma unroll
    for (int c = 0; c < FEAT; c++) {
        float t = s1[threadIdx.y][c] - s2[threadIdx.x][c];
        d += t * t;
    }
    float p = ex2f(fmaxf(-d * LOG2E, -100.f));
    int s  = i >> 6;
    int l  = (i >> 1) & 31;
    int rp = i & 1;
    int cc = j >> 1;
    int jp = j & 1;
    int t  = cc + l;
    g_Ds[(((size_t)s * D_TPAD + t) * 32 + l) * 4 + rp * 2 + jp] = p;
}

// ---------------- soft-DTW: probability-domain DP, memory ops hoisted off the superstep ----------------
// Per superstep: 3 shfl + FADD/FMUL/SEL + 1 fire-and-forget LDG. No stores, no fences.
// Lane 31 buffers its 8 (b0,b1,M) records per chunk in registers, then publishes them
// with 8 predicated STG.128 + ONE red.release per chunk.
// Flag semantics: after publisher chunk Cp (>=4), all col-pairs <= 8*Cp-24 are stored,
// so flag increments once per chunk for Cp>=4; consumer need=C+1 is satisfied at Cp=C+4.
__global__ void __launch_bounds__(32)
softdtw_prob(float* __restrict__ out) {
    const int s = blockIdx.x;
    const int lane = threadIdx.x;
    const int is31 = (lane == 31);
    const int isLast = (s == NSTRIP - 1);
    const int pubp = is31 & !isLast;

    float EA = 0.f, EB = 0.f, carry = 0.f;
    float sh0 = 0.f, sh1 = 0.f;
    int   M = 0, shM = 0;
    if (s == 0 && lane == 0) carry = 1.f;

    const float4* dsp = ((const float4*)g_Ds) + (size_t)s * D_TPAD * 32 + lane;
    float4 dbuf[4];
#pragma unroll
    for (int q = 0; q < 4; ++q) dbuf[q] = __ldg(dsp + (size_t)q * 32);

    const float4* rowprev = g_row4 + (size_t)(s - 1) * 1024;
    float4* rowmine = g_row4 + (size_t)s * 1024;
    int* myflag = &g_flag2[s * 32];
    const int* prevflag = &g_flag2[(s - 1) * 32];
    int flagseen = 0;

    float outE = 1.f; int outM = 0;

    float4 rp[8];
#pragma unroll
    for (int q = 0; q < 8; ++q) rp[q] = make_float4(0.f, 0.f, 0.f, 0.f);

    for (int C = 0; C < SS_CHUNKS; ++C) {
        if (s > 0 && C < 128) {
            const int need = C + 1;
            if (flagseen < need)
                while ((flagseen = ldacq(prevflag)) < need) { }
#pragma unroll
            for (int q = 0; q < 8; ++q) rp[q] = __ldg(&rowprev[C * 8 + q]);
            if (C == 0 && lane == 0) M = (int)rp[0].z;
        }

        float pub0[8], pub1[8]; int pubM[8];

#pragma unroll
        for (int q = 0; q < 8; ++q) {
            const int t = C * 8 + q;
            const int c = t - lane;
            float nE0 = __shfl_up_sync(0xffffffffu, sh0, 1);
            float nE1 = __shfl_up_sync(0xffffffffu, sh1, 1);
            int   nM  = __shfl_up_sync(0xffffffffu, shM, 1);
            if (lane == 0) { nE0 = rp[q].x; nE1 = rp[q].y; nM = (int)rp[q].z; }
            if (c < 0) M = nM;
            int dmm = M - nM;
            dmm = dmm < -126 ? -126 : (dmm > 126 ? 126 : dmm);
            float sc = __uint_as_float((unsigned)(dmm + 127) << 23);
            float FB0 = nE0 * sc;
            float FB1 = nE1 * sc;

            float4 p = dbuf[t & 3];
            dbuf[t & 3] = __ldg(dsp + (size_t)(t + 4) * 32);

            float a0 = p.x * ((carry + FB0) + EA);
            float a1 = p.y * ((FB0 + FB1) + a0);
            float b0 = p.z * ((EB + EA) + a0);
            float b1 = p.w * ((b0 + a1) + a0);

            const int active = (c >= 0) & (c < 1024);

            // register-buffered publish record (no memory ops here)
            pub0[q] = b0; pub1[q] = b1; pubM[q] = M;
            outE = (is31 & isLast & active & (c == 1023)) ? b1 : outE;
            outM = (is31 & isLast & active & (c == 1023)) ? M  : outM;

            sh0 = active ? b0 : sh0;
            sh1 = active ? b1 : sh1;
            shM = active ? M  : shM;

            int e = (__float_as_int(b1) >> 23) & 255;
            int doR = active & (e > 0) & (e < 254);
            int dm = doR ? (e - 127) : 0;
            float scR = __uint_as_float((unsigned)(254 - (doR ? e : 127)) << 23);
            EA = (active ? a1 : EA) * scR;
            EB = (active ? b1 : EB) * scR;
            carry = FB1 * scR;
            M = M - dm;
        }

        // once-per-chunk publish (lane 31 of non-last strips)
        {
            const int c0 = C * 8 - 31;
#pragma unroll
            for (int q = 0; q < 8; ++q) {
                const int cq = c0 + q;
                stg4_pred(rowmine + cq, pub0[q], pub1[q], (float)pubM[q],
                          pubp & (cq >= 0) & (cq < 1024));
            }
            red_rel_pred(myflag, pubp & (C >= 4));
        }
    }

    stg_pred(out, ((float)outM - lg2f(outE)) * LN2, is31 & isLast);
}

// ---------------- host orchestration ----------------
extern "C" void kernel_launch(void* const* d_in, const int* in_sizes, int n_in,
                              void* d_out, int out_size) {
    const float* x    = (const float*)d_in[0];
    const float* y    = (const float*)d_in[1];
    const float* Wih1 = (const float*)d_in[2];
    const float* Whh1 = (const float*)d_in[3];
    const float* bih1 = (const float*)d_in[4];
    const float* bhh1 = (const float*)d_in[5];
    const float* Wih2 = (const float*)d_in[6];
    const float* Whh2 = (const float*)d_in[7];
    const float* bih2 = (const float*)d_in[8];
    const float* bhh2 = (const float*)d_in[9];
    const float* W1   = (const float*)d_in[10];
    const float* b1   = (const float*)d_in[11];
    float* out = (float*)d_out;

    float *seq, *gi, *h1all, *whT1, *whT2;
    cudaGetSymbolAddress((void**)&seq,   g_seq);
    cudaGetSymbolAddress((void**)&gi,    g_gi);
    cudaGetSymbolAddress((void**)&h1all, g_h1all);
    cudaGetSymbolAddress((void**)&whT1,  g_WhhT1);
    cudaGetSymbolAddress((void**)&whT2,  g_WhhT2);

    const int GRU_SMEM = (32 * HID + 32 * G3) * 4;   // 64 KB
    cudaFuncSetAttribute(gru_layer_kernel,
                         cudaFuncAttributeMaxDynamicSharedMemorySize, GRU_SMEM);

    // 1) prep
    {
        int total = STEPS * BATCH * IN_F;
        prep_kernel<<<(total + 255) / 256, 256>>>(x, y, Whh1, Whh2);
    }

    // 2) layer-1 input gates: seq @ Wih1^T  (K=72)
    sgemm_db<8><<<dim3(G3 / 128, (STEPS * BATCH) / 128), 256>>>(
        seq, Wih1, bih1, gi, STEPS * BATCH, G3, IN_F);

    // 3) layer-1 recurrence
    gru_layer_kernel<<<BATCH / 32, 512, GRU_SMEM>>>(
        gi, (const float4*)whT1, bhh1, h1all, nullptr, nullptr);

    // 4) layer-2 input gates: h1all @ Wih2^T  (K=128)
    sgemm_db<16><<<dim3(G3 / 128, (STEPS * BATCH) / 128), 256>>>(
        h1all, Wih2, bih2, gi, STEPS * BATCH, G3, HID);

    // 5) layer-2 recurrence + fused feature projection
    gru_layer_kernel<<<BATCH / 32, 512, GRU_SMEM>>>(
        gi, (const float4*)whT2, bhh2, nullptr, W1, b1);

    // 6) pairwise distances -> probability domain, skewed block layout
    pairdist_kernel<<<dim3(NW / 32, NW / 32), dim3(32, 32)>>>();

    // 7) soft-DTW probability-domain wavefront (fence-free inner loop)
    softdtw_prob<<<NSTRIP, 32>>>(out);
}